// round 3
// baseline (speedup 1.0000x reference)
#include <cuda_runtime.h>
#include <math.h>

// ---------------- model constants ----------------
#define LNUM 6
#define DMODEL 1024
#define NH 16
#define NKV 4
#define HDIM 64
#define BATCH 2
#define SEQ 2048
#define TT (BATCH*SEQ)          // 4096 tokens
#define VSZ 50257
#define HSZ 4096
#define MLPD 3072
#define EPSF 1.1920929e-07f

// ---------------- scratch (device globals; no allocation allowed) ----------------
__device__ float g_X[TT*DMODEL];
__device__ float g_X0[TT*DMODEL];
__device__ float g_XR[TT*DMODEL];
__device__ float g_SK[LNUM*TT*DMODEL];
__device__ float g_Qb[TT*DMODEL];
__device__ float g_Kb[TT*NKV*HDIM];
__device__ float g_Vb[TT*NKV*HDIM];
__device__ float g_ATT[TT*DMODEL];
__device__ float g_MH[TT*MLPD];
__device__ float g_COS[SEQ*32];
__device__ float g_SIN[SEQ*32];
__device__ float g_SUMEXP[TT];
__device__ float g_TGT[TT];

// ---------------- helpers ----------------
__device__ __forceinline__ float block_sum_256(float v) {
    __shared__ float sh[8];
    #pragma unroll
    for (int o = 16; o; o >>= 1) v += __shfl_xor_sync(0xffffffffu, v, o);
    if ((threadIdx.x & 31) == 0) sh[threadIdx.x >> 5] = v;
    __syncthreads();
    if (threadIdx.x == 0) {
        float s = 0.f;
        #pragma unroll
        for (int i = 0; i < 8; i++) s += sh[i];
        sh[0] = s;
    }
    __syncthreads();
    return sh[0];
}

// ---------------- rope tables ----------------
__global__ void rope_table_kernel(float* __restrict__ cosT, float* __restrict__ sinT) {
    int idx = blockIdx.x * 256 + threadIdx.x;
    if (idx >= SEQ * 32) return;
    int t = idx >> 5, j = idx & 31;
    double f = pow(10000.0, -(double)j / 32.0);
    double a = (double)t * f;
    cosT[idx] = (float)cos(a);
    sinT[idx] = (float)sin(a);
}

// ---------------- embedding + rmsnorm ----------------
__global__ void embed_kernel(const int* __restrict__ ids, const float* __restrict__ u_emb,
                             const float* __restrict__ b_emb,
                             float* __restrict__ X, float* __restrict__ X0) {
    int t = blockIdx.x;
    int s = t & (SEQ - 1);
    int id = ids[t];
    int pi = (s == 0) ? 0 : ids[t - 1];
    int bi = ((pi % HSZ) * (VSZ % HSZ) % HSZ + id % HSZ) % HSZ;
    int tid = threadIdx.x;
    float v[4];
    float ssq = 0.f;
    #pragma unroll
    for (int i = 0; i < 4; i++) {
        int d = i * 256 + tid;
        float x = (d < 512) ? u_emb[(size_t)id * 512 + d] : b_emb[(size_t)bi * 512 + (d - 512)];
        v[i] = x; ssq += x * x;
    }
    float tot = block_sum_256(ssq);
    float r = rsqrtf(tot * (1.f / DMODEL) + EPSF);
    #pragma unroll
    for (int i = 0; i < 4; i++) {
        int d = i * 256 + tid;
        float o = v[i] * r;
        X[(size_t)t * DMODEL + d] = o;
        X0[(size_t)t * DMODEL + d] = o;
    }
}

// ---------------- residual mix (+optional skip) then rmsnorm ----------------
__global__ void mix_rmsn_kernel(float* __restrict__ X, const float* __restrict__ X0,
                                float* __restrict__ XR, const float* __restrict__ rm,
                                const float* __restrict__ skip, const float* __restrict__ sw) {
    int t = blockIdx.x, tid = threadIdx.x;
    float v[4]; float ssq = 0.f;
    #pragma unroll
    for (int i = 0; i < 4; i++) {
        int d = i * 256 + tid;
        size_t off = (size_t)t * DMODEL + d;
        float x = X[off];
        if (skip) x += sw[d] * skip[off];
        x = rm[d] * x + rm[DMODEL + d] * X0[off];
        v[i] = x; ssq += x * x;
    }
    float tot = block_sum_256(ssq);
    float r = rsqrtf(tot * (1.f / DMODEL) + EPSF);
    #pragma unroll
    for (int i = 0; i < 4; i++) {
        int d = i * 256 + tid;
        size_t off = (size_t)t * DMODEL + d;
        X[off] = v[i];
        XR[off] = v[i] * r;
    }
}

// ---------------- plain rmsnorm ----------------
__global__ void rmsn_kernel(const float* __restrict__ X, float* __restrict__ XR) {
    int t = blockIdx.x, tid = threadIdx.x;
    float v[4]; float ssq = 0.f;
    #pragma unroll
    for (int i = 0; i < 4; i++) {
        int d = i * 256 + tid;
        v[i] = X[(size_t)t * DMODEL + d];
        ssq += v[i] * v[i];
    }
    float tot = block_sum_256(ssq);
    float r = rsqrtf(tot * (1.f / DMODEL) + EPSF);
    #pragma unroll
    for (int i = 0; i < 4; i++) {
        int d = i * 256 + tid;
        XR[(size_t)t * DMODEL + d] = v[i] * r;
    }
}

// ---------------- per-head rmsnorm + rope (+qg for q) ----------------
__global__ void qkrope_kernel(float* __restrict__ Q, float* __restrict__ Kb,
                              const float* __restrict__ cosT, const float* __restrict__ sinT,
                              const float* __restrict__ qg) {
    int gw = blockIdx.x * 8 + (threadIdx.x >> 5);
    int lane = threadIdx.x & 31;
    const int NQ = TT * NH;
    float* base; float gain; int t;
    if (gw < NQ) {
        t = gw >> 4; int h = gw & 15;
        base = Q + (size_t)t * DMODEL + h * HDIM;
        gain = qg[h];
    } else {
        int g2 = gw - NQ;
        if (g2 >= TT * NKV) return;
        t = g2 >> 2; int h = g2 & 3;
        base = Kb + (size_t)t * (NKV * HDIM) + h * HDIM;
        gain = 1.f;
    }
    int s = t & (SEQ - 1);
    float v1 = base[lane], v2 = base[lane + 32];
    float ssq = v1 * v1 + v2 * v2;
    #pragma unroll
    for (int off = 16; off; off >>= 1) ssq += __shfl_xor_sync(0xffffffffu, ssq, off);
    float r = rsqrtf(ssq * (1.f / HDIM) + EPSF);
    v1 *= r; v2 *= r;
    float c = cosT[s * 32 + lane], sn = sinT[s * 32 + lane];
    float o1 = v1 * c + v2 * sn;
    float o2 = -v1 * sn + v2 * c;
    base[lane] = o1 * gain;
    base[lane + 32] = o2 * gain;
}

// ---------------- generic SGEMM: C[M,N] = A[M,K(lda)] @ W[N,K]^T ----------------
// mode 0: C = acc
// mode 1: C += scale[n]*acc   (residual fuse, in-place)
// mode 2: C = relu(acc)^2
// mode 3: loss: atomicAdd(sumexp[m], sum_n exp(30*tanh(acc/30)))  (no store)
__global__ void __launch_bounds__(256) gemm_kernel(
    const float* __restrict__ A, int lda, const float* __restrict__ W,
    float* __restrict__ C, const float* __restrict__ scale, float* __restrict__ sumexp,
    int M, int N, int K, int mode)
{
    __shared__ float As[8][132];
    __shared__ float Ws[8][132];
    int tid = threadIdx.x;
    int tx = tid & 15, ty = tid >> 4;
    int m0 = blockIdx.y * 128, n0 = blockIdx.x * 128;
    int arow = tid >> 1;
    int acol = (tid & 1) * 4;
    const float* Ap = A + (size_t)(m0 + arow) * lda + acol;
    int wrow = n0 + arow;
    bool wv = wrow < N;
    const float* Wp = W + (size_t)(wv ? wrow : 0) * K + acol;
    float acc[8][8];
    #pragma unroll
    for (int i = 0; i < 8; i++)
        #pragma unroll
        for (int j = 0; j < 8; j++) acc[i][j] = 0.f;

    for (int k0 = 0; k0 < K; k0 += 8) {
        float4 av = *(const float4*)(Ap + k0);
        float4 wvv = wv ? *(const float4*)(Wp + k0) : make_float4(0.f, 0.f, 0.f, 0.f);
        __syncthreads();
        As[acol + 0][arow] = av.x; As[acol + 1][arow] = av.y;
        As[acol + 2][arow] = av.z; As[acol + 3][arow] = av.w;
        Ws[acol + 0][arow] = wvv.x; Ws[acol + 1][arow] = wvv.y;
        Ws[acol + 2][arow] = wvv.z; Ws[acol + 3][arow] = wvv.w;
        __syncthreads();
        #pragma unroll
        for (int kk = 0; kk < 8; kk++) {
            float4 a0 = *(const float4*)&As[kk][ty * 8];
            float4 a1 = *(const float4*)&As[kk][ty * 8 + 4];
            float4 w0 = *(const float4*)&Ws[kk][tx * 8];
            float4 w1 = *(const float4*)&Ws[kk][tx * 8 + 4];
            float ar_[8] = {a0.x, a0.y, a0.z, a0.w, a1.x, a1.y, a1.z, a1.w};
            float wr_[8] = {w0.x, w0.y, w0.z, w0.w, w1.x, w1.y, w1.z, w1.w};
            #pragma unroll
            for (int i = 0; i < 8; i++)
                #pragma unroll
                for (int j = 0; j < 8; j++)
                    acc[i][j] += ar_[i] * wr_[j];
        }
    }

    if (mode == 3) {
        #pragma unroll
        for (int i = 0; i < 8; i++) {
            float s = 0.f;
            #pragma unroll
            for (int j = 0; j < 8; j++) {
                int n = n0 + tx * 8 + j;
                if (n < N) {
                    float lg = 30.f * tanhf(acc[i][j] * (1.f / 30.f));
                    s += __expf(lg);
                }
            }
            #pragma unroll
            for (int off = 8; off; off >>= 1) s += __shfl_xor_sync(0xffffffffu, s, off);
            if (tx == 0) atomicAdd(&sumexp[m0 + ty * 8 + i], s);
        }
        return;
    }
    #pragma unroll
    for (int i = 0; i < 8; i++) {
        int m = m0 + ty * 8 + i;
        float* Cp = C + (size_t)m * N + n0 + tx * 8;
        if (mode == 0) {
            *(float4*)Cp       = make_float4(acc[i][0], acc[i][1], acc[i][2], acc[i][3]);
            *(float4*)(Cp + 4) = make_float4(acc[i][4], acc[i][5], acc[i][6], acc[i][7]);
        } else if (mode == 1) {
            float4 s0 = *(const float4*)(scale + n0 + tx * 8);
            float4 s1 = *(const float4*)(scale + n0 + tx * 8 + 4);
            float4 c0 = *(const float4*)Cp;
            float4 c1 = *(const float4*)(Cp + 4);
            c0.x += s0.x * acc[i][0]; c0.y += s0.y * acc[i][1];
            c0.z += s0.z * acc[i][2]; c0.w += s0.w * acc[i][3];
            c1.x += s1.x * acc[i][4]; c1.y += s1.y * acc[i][5];
            c1.z += s1.z * acc[i][6]; c1.w += s1.w * acc[i][7];
            *(float4*)Cp = c0; *(float4*)(Cp + 4) = c1;
        } else { // mode 2: relu^2
            float4 c0, c1;
            float r0 = fmaxf(acc[i][0], 0.f), r1 = fmaxf(acc[i][1], 0.f);
            float r2 = fmaxf(acc[i][2], 0.f), r3 = fmaxf(acc[i][3], 0.f);
            float r4 = fmaxf(acc[i][4], 0.f), r5 = fmaxf(acc[i][5], 0.f);
            float r6 = fmaxf(acc[i][6], 0.f), r7 = fmaxf(acc[i][7], 0.f);
            c0 = make_float4(r0 * r0, r1 * r1, r2 * r2, r3 * r3);
            c1 = make_float4(r4 * r4, r5 * r5, r6 * r6, r7 * r7);
            *(float4*)Cp = c0; *(float4*)(Cp + 4) = c1;
        }
    }
}

// ---------------- causal flash attention (fp32, GQA) ----------------
// grid (32 qtiles, B*NH=32), block 256 (tx=16, ty=16)
__global__ void __launch_bounds__(256) flash_kernel(
    const float* __restrict__ Q, const float* __restrict__ K,
    const float* __restrict__ V, float* __restrict__ O)
{
    __shared__ float Qs[64][64];
    __shared__ float Ks[32][68];
    __shared__ float Vs[32][68];
    __shared__ float Ps[64][33];
    int qt = blockIdx.x;
    int bh = blockIdx.y;
    int b = bh >> 4, head = bh & 15, kvh = head >> 2;
    int tid = threadIdx.x, tx = tid & 15, ty = tid >> 4;
    int t0 = b * SEQ + qt * 64;
    #pragma unroll
    for (int i = 0; i < 4; i++) {
        int idx = tid + i * 256;
        int r = idx >> 4, c4 = (idx & 15) * 4;
        float4 q4 = *(const float4*)(Q + (size_t)(t0 + r) * DMODEL + head * HDIM + c4);
        q4.x *= 0.125f; q4.y *= 0.125f; q4.z *= 0.125f; q4.w *= 0.125f;
        *(float4*)&Qs[r][c4] = q4;
    }
    float m[4], l[4], o[4][4];
    #pragma unroll
    for (int i = 0; i < 4; i++) {
        m[i] = -1e30f; l[i] = 0.f;
        #pragma unroll
        for (int c = 0; c < 4; c++) o[i][c] = 0.f;
    }
    int nkt = (qt + 1) * 2;
    for (int kt = 0; kt < nkt; kt++) {
        __syncthreads();
        int k0 = b * SEQ + kt * 32;
        #pragma unroll
        for (int i = 0; i < 2; i++) {
            int idx = tid + i * 256;
            int r = idx >> 4, c4 = (idx & 15) * 4;
            *(float4*)&Ks[r][c4] = *(const float4*)(K + (size_t)(k0 + r) * (NKV * HDIM) + kvh * HDIM + c4);
            *(float4*)&Vs[r][c4] = *(const float4*)(V + (size_t)(k0 + r) * (NKV * HDIM) + kvh * HDIM + c4);
        }
        __syncthreads();
        float sc[4][2];
        #pragma unroll
        for (int i = 0; i < 4; i++) { sc[i][0] = 0.f; sc[i][1] = 0.f; }
        #pragma unroll
        for (int d = 0; d < 64; d += 4) {
            float4 ka = *(const float4*)&Ks[tx * 2][d];
            float4 kb = *(const float4*)&Ks[tx * 2 + 1][d];
            #pragma unroll
            for (int i = 0; i < 4; i++) {
                float4 qv = *(const float4*)&Qs[ty * 4 + i][d];
                sc[i][0] += qv.x * ka.x + qv.y * ka.y + qv.z * ka.z + qv.w * ka.w;
                sc[i][1] += qv.x * kb.x + qv.y * kb.y + qv.z * kb.z + qv.w * kb.w;
            }
        }
        int kg0 = kt * 32 + tx * 2;
        #pragma unroll
        for (int i = 0; i < 4; i++) {
            int qrow = qt * 64 + ty * 4 + i;
            if (kg0 > qrow)     sc[i][0] = -1e30f;
            if (kg0 + 1 > qrow) sc[i][1] = -1e30f;
            float tm = fmaxf(sc[i][0], sc[i][1]);
            #pragma unroll
            for (int off = 8; off; off >>= 1) tm = fmaxf(tm, __shfl_xor_sync(0xffffffffu, tm, off));
            float mn = fmaxf(m[i], tm);
            float al = __expf(m[i] - mn);
            float p0 = __expf(sc[i][0] - mn);
            float p1 = __expf(sc[i][1] - mn);
            float rs = p0 + p1;
            #pragma unroll
            for (int off = 8; off; off >>= 1) rs += __shfl_xor_sync(0xffffffffu, rs, off);
            l[i] = l[i] * al + rs;
            m[i] = mn;
            #pragma unroll
            for (int c = 0; c < 4; c++) o[i][c] *= al;
            Ps[ty * 4 + i][tx * 2]     = p0;
            Ps[ty * 4 + i][tx * 2 + 1] = p1;
        }
        __syncthreads();
        #pragma unroll 8
        for (int k = 0; k < 32; k++) {
            float4 vv = *(const float4*)&Vs[k][tx * 4];
            #pragma unroll
            for (int i = 0; i < 4; i++) {
                float p = Ps[ty * 4 + i][k];
                o[i][0] += p * vv.x; o[i][1] += p * vv.y;
                o[i][2] += p * vv.z; o[i][3] += p * vv.w;
            }
        }
    }
    #pragma unroll
    for (int i = 0; i < 4; i++) {
        float inv = 1.f / l[i];
        int row = t0 + ty * 4 + i;
        float4 ov = make_float4(o[i][0] * inv, o[i][1] * inv, o[i][2] * inv, o[i][3] * inv);
        *(float4*)(O + (size_t)row * DMODEL + head * HDIM + tx * 4) = ov;
    }
}

// ---------------- misc small kernels ----------------
__global__ void copy_kernel(float4* __restrict__ dst, const float4* __restrict__ src, int n4) {
    int i = blockIdx.x * blockDim.x + threadIdx.x;
    if (i < n4) dst[i] = src[i];
}
__global__ void zero_kernel(float* __restrict__ p, int n) {
    int i = blockIdx.x * blockDim.x + threadIdx.x;
    if (i < n) p[i] = 0.f;
}
__global__ void tgt_kernel(const float* __restrict__ XR, const float* __restrict__ u_emb,
                           const int* __restrict__ y, float* __restrict__ tgt) {
    int row = blockIdx.x * 4 + (threadIdx.x >> 5);
    int lane = threadIdx.x & 31;
    if (row >= TT) return;
    int t = y[row];
    const float* h = XR + (size_t)row * DMODEL;
    const float* u = u_emb + (size_t)t * 512;
    float s = 0.f;
    for (int i = lane * 4; i < 512; i += 128) {
        float4 hv = *(const float4*)(h + i);
        float4 uv = *(const float4*)(u + i);
        s += hv.x * uv.x + hv.y * uv.y + hv.z * uv.z + hv.w * uv.w;
    }
    #pragma unroll
    for (int off = 16; off; off >>= 1) s += __shfl_xor_sync(0xffffffffu, s, off);
    if (lane == 0) tgt[row] = 30.f * tanhf(s * (1.f / 30.f));
}
__global__ void loss_kernel(const float* __restrict__ sumexp, const float* __restrict__ tgt,
                            float* __restrict__ out) {
    float s = 0.f;
    for (int i = threadIdx.x; i < TT; i += 256)
        s += logf(sumexp[i]) - tgt[i];
    float tot = block_sum_256(s);
    if (threadIdx.x == 0) out[0] = tot * (1.f / TT);
}

// ---------------- host orchestration ----------------
static inline void gemm_launch(const float* A, int lda, const float* W, float* C,
                               const float* scale, float* sumexp,
                               int M, int N, int K, int mode) {
    dim3 grid((N + 127) / 128, M / 128);
    gemm_kernel<<<grid, 256>>>(A, lda, W, C, scale, sumexp, M, N, K, mode);
}

extern "C" void kernel_launch(void* const* d_in, const int* in_sizes, int n_in,
                              void* d_out, int out_size) {
    const int*   ids     = (const int*)d_in[0];
    const int*   y       = (const int*)d_in[1];
    const float* u_emb   = (const float*)d_in[2];
    const float* b_emb   = (const float*)d_in[3];
    const float* Wq      = (const float*)d_in[4];
    const float* Wk      = (const float*)d_in[5];
    const float* Wv      = (const float*)d_in[6];
    const float* Wo      = (const float*)d_in[7];
    const float* qg      = (const float*)d_in[8];
    const float* a_scale = (const float*)d_in[9];
    const float* m_scale = (const float*)d_in[10];
    const float* rm      = (const float*)d_in[11];
    const float* Wf      = (const float*)d_in[12];
    const float* Wo2     = (const float*)d_in[13];
    const float* sw      = (const float*)d_in[14];

    float *X, *X0, *XR, *SK, *Qb, *Kb, *Vb, *ATT, *MH, *COS, *SIN, *SUM, *TGT;
    cudaGetSymbolAddress((void**)&X,   g_X);
    cudaGetSymbolAddress((void**)&X0,  g_X0);
    cudaGetSymbolAddress((void**)&XR,  g_XR);
    cudaGetSymbolAddress((void**)&SK,  g_SK);
    cudaGetSymbolAddress((void**)&Qb,  g_Qb);
    cudaGetSymbolAddress((void**)&Kb,  g_Kb);
    cudaGetSymbolAddress((void**)&Vb,  g_Vb);
    cudaGetSymbolAddress((void**)&ATT, g_ATT);
    cudaGetSymbolAddress((void**)&MH,  g_MH);
    cudaGetSymbolAddress((void**)&COS, g_COS);
    cudaGetSymbolAddress((void**)&SIN, g_SIN);
    cudaGetSymbolAddress((void**)&SUM, g_SUMEXP);
    cudaGetSymbolAddress((void**)&TGT, g_TGT);

    rope_table_kernel<<<(SEQ * 32 + 255) / 256, 256>>>(COS, SIN);
    embed_kernel<<<TT, 256>>>(ids, u_emb, b_emb, X, X0);

    auto run_block = [&](int l, const float* skip, const float* swv) {
        mix_rmsn_kernel<<<TT, 256>>>(X, X0, XR, rm + (size_t)l * 2 * DMODEL, skip, swv);
        gemm_launch(XR, DMODEL, Wq + (size_t)l * DMODEL * DMODEL, Qb, nullptr, nullptr, TT, DMODEL, DMODEL, 0);
        gemm_launch(XR, DMODEL, Wk + (size_t)l * NKV * HDIM * DMODEL, Kb, nullptr, nullptr, TT, NKV * HDIM, DMODEL, 0);
        gemm_launch(XR, DMODEL, Wv + (size_t)l * NKV * HDIM * DMODEL, Vb, nullptr, nullptr, TT, NKV * HDIM, DMODEL, 0);
        qkrope_kernel<<<(TT * NH + TT * NKV) / 8 / 32 * 32 / 32 + 0, 256>>>(Qb, Kb, COS, SIN, qg + (size_t)l * NH);
        flash_kernel<<<dim3(32, 32), 256>>>(Qb, Kb, Vb, ATT);
        gemm_launch(ATT, DMODEL, Wo + (size_t)l * DMODEL * DMODEL, X, a_scale + (size_t)l * DMODEL, nullptr, TT, DMODEL, DMODEL, 1);
        rmsn_kernel<<<TT, 256>>>(X, XR);
        gemm_launch(XR, DMODEL, Wf + (size_t)l * MLPD * DMODEL, MH, nullptr, nullptr, TT, MLPD, DMODEL, 2);
        gemm_launch(MH, MLPD, Wo2 + (size_t)l * DMODEL * MLPD, X, m_scale + (size_t)l * DMODEL, nullptr, TT, DMODEL, MLPD, 1);
    };

    // forward pass + skip stash
    for (int i = 0; i < LNUM; i++) {
        run_block(i, nullptr, nullptr);
        copy_kernel<<<(TT * DMODEL / 4 + 255) / 256, 256>>>(
            (float4*)(SK + (size_t)i * TT * DMODEL), (const float4*)X, TT * DMODEL / 4);
    }
    // reverse pass with skips: h = h + sw[i]*sk[L-1-i]; block params j = L-1-i
    for (int i = 0; i < LNUM; i++) {
        int j = LNUM - 1 - i;
        run_block(j, SK + (size_t)j * TT * DMODEL, sw + (size_t)i * DMODEL);
    }

    // final norm + loss
    rmsn_kernel<<<TT, 256>>>(X, XR);
    zero_kernel<<<(TT + 255) / 256, 256>>>(SUM, TT);
    gemm_launch(XR, DMODEL, u_emb, nullptr, nullptr, SUM, TT, VSZ, 512, 3);
    tgt_kernel<<<TT / 4, 128>>>(XR, u_emb, y, TGT);
    loss_kernel<<<1, 256>>>(SUM, TGT, (float*)d_out);
}

// round 4
// speedup vs baseline: 1.4766x; 1.4766x over previous
#include <cuda_runtime.h>
#include <math.h>
#include <stdint.h>

// ---------------- model constants ----------------
#define LNUM 6
#define DMODEL 1024
#define NH 16
#define NKV 4
#define HDIM 64
#define BATCH 2
#define SEQ 2048
#define TT (BATCH*SEQ)          // 4096 tokens
#define VSZ 50257
#define HSZ 4096
#define MLPD 3072
#define QKVD 1536               // 1024 + 256 + 256
#define EPSF 1.1920929e-07f

// ---------------- scratch (device globals; no allocation allowed) ----------------
__device__ float g_X[TT*DMODEL];
__device__ float g_X0[TT*DMODEL];
__device__ float g_XR[TT*DMODEL];
__device__ float g_SK[LNUM*TT*DMODEL];
__device__ float g_QKV[TT*QKVD];
__device__ float g_ATT[TT*DMODEL];
__device__ float g_MH[TT*MLPD];
__device__ float g_WQKV[(size_t)LNUM*QKVD*DMODEL];
__device__ float g_COS[SEQ*32];
__device__ float g_SIN[SEQ*32];
__device__ float g_SUMEXP[TT];
__device__ float g_TGT[TT];

// ---------------- helpers ----------------
__device__ __forceinline__ float block_sum_256(float v) {
    __shared__ float sh[8];
    #pragma unroll
    for (int o = 16; o; o >>= 1) v += __shfl_xor_sync(0xffffffffu, v, o);
    if ((threadIdx.x & 31) == 0) sh[threadIdx.x >> 5] = v;
    __syncthreads();
    if (threadIdx.x == 0) {
        float s = 0.f;
        #pragma unroll
        for (int i = 0; i < 8; i++) s += sh[i];
        sh[0] = s;
    }
    __syncthreads();
    return sh[0];
}

__device__ __forceinline__ uint32_t f2tf(float x) {
    uint32_t r;
    asm("cvt.rna.tf32.f32 %0, %1;" : "=r"(r) : "f"(x));
    return r;
}

__device__ __forceinline__ void mma_tf32(float* c, uint32_t a0, uint32_t a1,
                                         uint32_t a2, uint32_t a3,
                                         uint32_t b0, uint32_t b1) {
    asm volatile(
        "mma.sync.aligned.m16n8k8.row.col.f32.tf32.tf32.f32 "
        "{%0,%1,%2,%3}, {%4,%5,%6,%7}, {%8,%9}, {%0,%1,%2,%3};"
        : "+f"(c[0]), "+f"(c[1]), "+f"(c[2]), "+f"(c[3])
        : "r"(a0), "r"(a1), "r"(a2), "r"(a3), "r"(b0), "r"(b1));
}

// ---------------- rope tables ----------------
__global__ void rope_table_kernel(float* __restrict__ cosT, float* __restrict__ sinT) {
    int idx = blockIdx.x * 256 + threadIdx.x;
    if (idx >= SEQ * 32) return;
    int t = idx >> 5, j = idx & 31;
    double f = pow(10000.0, -(double)j / 32.0);
    double a = (double)t * f;
    cosT[idx] = (float)cos(a);
    sinT[idx] = (float)sin(a);
}

// ---------------- pack Wq/Wk/Wv -> WQKV[l][1536][1024] ----------------
__global__ void pack_qkv_kernel(const float* __restrict__ Wq, const float* __restrict__ Wk,
                                const float* __restrict__ Wv, float4* __restrict__ out) {
    const int ROWF4 = DMODEL / 4;
    const int TOT = LNUM * QKVD * ROWF4;
    int i = blockIdx.x * 256 + threadIdx.x;
    if (i >= TOT) return;
    int rowg = i / ROWF4, c = i % ROWF4;
    int l = rowg / QKVD, r = rowg % QKVD;
    const float4* src;
    if (r < 1024)      src = (const float4*)(Wq + ((size_t)l * 1024 + r) * DMODEL);
    else if (r < 1280) src = (const float4*)(Wk + ((size_t)l * 256 + (r - 1024)) * DMODEL);
    else               src = (const float4*)(Wv + ((size_t)l * 256 + (r - 1280)) * DMODEL);
    out[i] = src[c];
}

// ---------------- embedding + rmsnorm ----------------
__global__ void embed_kernel(const int* __restrict__ ids, const float* __restrict__ u_emb,
                             const float* __restrict__ b_emb,
                             float* __restrict__ X, float* __restrict__ X0) {
    int t = blockIdx.x;
    int s = t & (SEQ - 1);
    int id = ids[t];
    int pi = (s == 0) ? 0 : ids[t - 1];
    int bi = ((pi % HSZ) * (VSZ % HSZ) % HSZ + id % HSZ) % HSZ;
    int tid = threadIdx.x;
    float v[4];
    float ssq = 0.f;
    #pragma unroll
    for (int i = 0; i < 4; i++) {
        int d = i * 256 + tid;
        float x = (d < 512) ? u_emb[(size_t)id * 512 + d] : b_emb[(size_t)bi * 512 + (d - 512)];
        v[i] = x; ssq += x * x;
    }
    float tot = block_sum_256(ssq);
    float r = rsqrtf(tot * (1.f / DMODEL) + EPSF);
    #pragma unroll
    for (int i = 0; i < 4; i++) {
        int d = i * 256 + tid;
        float o = v[i] * r;
        X[(size_t)t * DMODEL + d] = o;
        X0[(size_t)t * DMODEL + d] = o;
    }
}

// ---------------- residual mix (+optional skip) then rmsnorm ----------------
__global__ void mix_rmsn_kernel(float* __restrict__ X, const float* __restrict__ X0,
                                float* __restrict__ XR, const float* __restrict__ rm,
                                const float* __restrict__ skip, const float* __restrict__ sw) {
    int t = blockIdx.x, tid = threadIdx.x;
    float v[4]; float ssq = 0.f;
    #pragma unroll
    for (int i = 0; i < 4; i++) {
        int d = i * 256 + tid;
        size_t off = (size_t)t * DMODEL + d;
        float x = X[off];
        if (skip) x += sw[d] * skip[off];
        x = rm[d] * x + rm[DMODEL + d] * X0[off];
        v[i] = x; ssq += x * x;
    }
    float tot = block_sum_256(ssq);
    float r = rsqrtf(tot * (1.f / DMODEL) + EPSF);
    #pragma unroll
    for (int i = 0; i < 4; i++) {
        int d = i * 256 + tid;
        size_t off = (size_t)t * DMODEL + d;
        X[off] = v[i];
        XR[off] = v[i] * r;
    }
}

// ---------------- plain rmsnorm ----------------
__global__ void rmsn_kernel(const float* __restrict__ X, float* __restrict__ XR) {
    int t = blockIdx.x, tid = threadIdx.x;
    float v[4]; float ssq = 0.f;
    #pragma unroll
    for (int i = 0; i < 4; i++) {
        int d = i * 256 + tid;
        v[i] = X[(size_t)t * DMODEL + d];
        ssq += v[i] * v[i];
    }
    float tot = block_sum_256(ssq);
    float r = rsqrtf(tot * (1.f / DMODEL) + EPSF);
    #pragma unroll
    for (int i = 0; i < 4; i++) {
        int d = i * 256 + tid;
        XR[(size_t)t * DMODEL + d] = v[i] * r;
    }
}

// ---------------- per-head rmsnorm + rope (+qg for q), QKV packed layout ----------------
__global__ void qkrope_kernel(float* __restrict__ QKV,
                              const float* __restrict__ cosT, const float* __restrict__ sinT,
                              const float* __restrict__ qg) {
    int gw = blockIdx.x * 8 + (threadIdx.x >> 5);
    int lane = threadIdx.x & 31;
    const int NQ = TT * NH;
    float* base; float gain; int t;
    if (gw < NQ) {
        t = gw >> 4; int h = gw & 15;
        base = QKV + (size_t)t * QKVD + h * HDIM;
        gain = qg[h];
    } else {
        int g2 = gw - NQ;
        if (g2 >= TT * NKV) return;
        t = g2 >> 2; int h = g2 & 3;
        base = QKV + (size_t)t * QKVD + 1024 + h * HDIM;
        gain = 1.f;
    }
    int s = t & (SEQ - 1);
    float v1 = base[lane], v2 = base[lane + 32];
    float ssq = v1 * v1 + v2 * v2;
    #pragma unroll
    for (int off = 16; off; off >>= 1) ssq += __shfl_xor_sync(0xffffffffu, ssq, off);
    float r = rsqrtf(ssq * (1.f / HDIM) + EPSF);
    v1 *= r; v2 *= r;
    float c = cosT[s * 32 + lane], sn = sinT[s * 32 + lane];
    float o1 = v1 * c + v2 * sn;
    float o2 = -v1 * sn + v2 * c;
    base[lane] = o1 * gain;
    base[lane + 32] = o2 * gain;
}

// ---------------- TF32 tensor-core GEMM: C[M,N] = A[M,K(lda)] @ W[N,K]^T ----------------
// Block 128x128, BK=16, 8 warps (warp tile 32x64), mma.m16n8k8.tf32.
// mode 0: C = acc              mode 1: C += scale[n]*acc (in-place)
// mode 2: C = relu(acc)^2      mode 3: atomicAdd(sumexp[m], sum_n exp(30*tanh(acc/30)))
__global__ void __launch_bounds__(256) gemm_tf32_kernel(
    const float* __restrict__ A, int lda, const float* __restrict__ W,
    float* __restrict__ C, int ldc, const float* __restrict__ scale,
    float* __restrict__ sumexp, int M, int N, int K, int mode)
{
    // fragment-permuted staging: A-frag = 1 LDS.128/lane, B-frag = 1 LDS.64/lane
    __shared__ uint32_t As[8][2][32][4];   // [mtile][kstep][lane][si]  si = (row>=8)*2 + (col>=4)
    __shared__ uint32_t Bs[16][32][4];     // [ntile][lane][ks*2 + (k>=4)]

    int tid = threadIdx.x;
    int lane = tid & 31, wid = tid >> 5;
    int wm = wid & 3, wn = wid >> 2;       // warp tile: rows wm*32, cols wn*64
    int m0 = blockIdx.y * 128, n0 = blockIdx.x * 128;

    // global-load assignment: each thread loads one row, 8 consecutive k (one ks)
    int ar = tid >> 1;            // 0..127
    int ks = tid & 1;             // which k-half of BK
    int ac = ks * 8;
    const float* Ap = A + (size_t)(m0 + ar) * lda + ac;
    int wrow = n0 + ar;
    int wsafe = (wrow < N) ? wrow : (N - 1);
    const float* Wp = W + (size_t)wsafe * K + ac;

    float acc[2][8][4];
    #pragma unroll
    for (int i = 0; i < 2; i++)
        #pragma unroll
        for (int j = 0; j < 8; j++)
            #pragma unroll
            for (int c = 0; c < 4; c++) acc[i][j][c] = 0.f;

    int mt = ar >> 4, rr = ar & 15;
    int lbA = (rr & 7) * 4, rg = rr >> 3;
    int nt = ar >> 3, nn = ar & 7;
    int lbB = nn * 4;

    float4 pa0 = *(const float4*)(Ap);
    float4 pa1 = *(const float4*)(Ap + 4);
    float4 pw0 = *(const float4*)(Wp);
    float4 pw1 = *(const float4*)(Wp + 4);

    for (int k0 = 0; k0 < K; k0 += 16) {
        __syncthreads();
        // scatter-store A: element (rr, cc) -> lane (rr&7)*4+(cc&3), si = rg*2 + (cc>=4)
        *(uint2*)&As[mt][ks][lbA + 0][rg * 2] = make_uint2(f2tf(pa0.x), f2tf(pa1.x));
        *(uint2*)&As[mt][ks][lbA + 1][rg * 2] = make_uint2(f2tf(pa0.y), f2tf(pa1.y));
        *(uint2*)&As[mt][ks][lbA + 2][rg * 2] = make_uint2(f2tf(pa0.z), f2tf(pa1.z));
        *(uint2*)&As[mt][ks][lbA + 3][rg * 2] = make_uint2(f2tf(pa0.w), f2tf(pa1.w));
        // scatter-store B: element (nn, kk) -> lane nn*4+(kk&3), reg = ks*2 + (kk>=4)
        *(uint2*)&Bs[nt][lbB + 0][ks * 2] = make_uint2(f2tf(pw0.x), f2tf(pw1.x));
        *(uint2*)&Bs[nt][lbB + 1][ks * 2] = make_uint2(f2tf(pw0.y), f2tf(pw1.y));
        *(uint2*)&Bs[nt][lbB + 2][ks * 2] = make_uint2(f2tf(pw0.z), f2tf(pw1.z));
        *(uint2*)&Bs[nt][lbB + 3][ks * 2] = make_uint2(f2tf(pw0.w), f2tf(pw1.w));
        __syncthreads();

        if (k0 + 16 < K) {   // prefetch next tile
            pa0 = *(const float4*)(Ap + k0 + 16);
            pa1 = *(const float4*)(Ap + k0 + 20);
            pw0 = *(const float4*)(Wp + k0 + 16);
            pw1 = *(const float4*)(Wp + k0 + 20);
        }

        uint4 af[2][2];
        #pragma unroll
        for (int i = 0; i < 2; i++)
            #pragma unroll
            for (int s = 0; s < 2; s++)
                af[i][s] = *(const uint4*)&As[2 * wm + i][s][lane][0];

        #pragma unroll
        for (int s = 0; s < 2; s++) {
            #pragma unroll
            for (int j = 0; j < 8; j++) {
                uint2 b = *(const uint2*)&Bs[8 * wn + j][lane][s * 2];
                // fragment order a0..a3 = si0, si2, si1, si3
                mma_tf32(acc[0][j], af[0][s].x, af[0][s].z, af[0][s].y, af[0][s].w, b.x, b.y);
                mma_tf32(acc[1][j], af[1][s].x, af[1][s].z, af[1][s].y, af[1][s].w, b.x, b.y);
            }
        }
    }

    int r0 = lane >> 2, c0v = (lane & 3) * 2;

    if (mode == 3) {
        #pragma unroll
        for (int i = 0; i < 2; i++) {
            #pragma unroll
            for (int h = 0; h < 2; h++) {
                float s = 0.f;
                #pragma unroll
                for (int j = 0; j < 8; j++) {
                    int col = n0 + (8 * wn + j) * 8 + c0v;
                    if (col < N)     s += __expf(30.f * tanhf(acc[i][j][h * 2 + 0] * (1.f / 30.f)));
                    if (col + 1 < N) s += __expf(30.f * tanhf(acc[i][j][h * 2 + 1] * (1.f / 30.f)));
                }
                s += __shfl_xor_sync(0xffffffffu, s, 1);
                s += __shfl_xor_sync(0xffffffffu, s, 2);
                if ((lane & 3) == 0) {
                    int row = m0 + (2 * wm + i) * 16 + r0 + h * 8;
                    atomicAdd(&sumexp[row], s);
                }
            }
        }
        return;
    }

    #pragma unroll
    for (int i = 0; i < 2; i++) {
        int mrow = m0 + (2 * wm + i) * 16 + r0;
        #pragma unroll
        for (int j = 0; j < 8; j++) {
            int col = n0 + (8 * wn + j) * 8 + c0v;
            float* p0 = C + (size_t)mrow * ldc + col;
            float* p1 = p0 + (size_t)8 * ldc;
            if (mode == 0) {
                *(float2*)p0 = make_float2(acc[i][j][0], acc[i][j][1]);
                *(float2*)p1 = make_float2(acc[i][j][2], acc[i][j][3]);
            } else if (mode == 1) {
                float2 sc = *(const float2*)(scale + col);
                float2 v0 = *(const float2*)p0;
                float2 v1 = *(const float2*)p1;
                v0.x += sc.x * acc[i][j][0]; v0.y += sc.y * acc[i][j][1];
                v1.x += sc.x * acc[i][j][2]; v1.y += sc.y * acc[i][j][3];
                *(float2*)p0 = v0; *(float2*)p1 = v1;
            } else { // relu^2
                float a = fmaxf(acc[i][j][0], 0.f), b = fmaxf(acc[i][j][1], 0.f);
                float c = fmaxf(acc[i][j][2], 0.f), d = fmaxf(acc[i][j][3], 0.f);
                *(float2*)p0 = make_float2(a * a, b * b);
                *(float2*)p1 = make_float2(c * c, d * d);
            }
        }
    }
}

// ---------------- causal flash attention (fp32, GQA), packed QKV layout ----------------
// grid (32 qtiles, B*NH=32), block 256 (tx=16, ty=16)
__global__ void __launch_bounds__(256) flash_kernel(
    const float* __restrict__ QKV, float* __restrict__ O)
{
    __shared__ float Qs[64][64];
    __shared__ float Ks[32][68];
    __shared__ float Vs[32][68];
    __shared__ float Ps[64][33];
    int qt = blockIdx.x;
    int bh = blockIdx.y;
    int b = bh >> 4, head = bh & 15, kvh = head >> 2;
    int tid = threadIdx.x, tx = tid & 15, ty = tid >> 4;
    int t0 = b * SEQ + qt * 64;
    #pragma unroll
    for (int i = 0; i < 4; i++) {
        int idx = tid + i * 256;
        int r = idx >> 4, c4 = (idx & 15) * 4;
        float4 q4 = *(const float4*)(QKV + (size_t)(t0 + r) * QKVD + head * HDIM + c4);
        q4.x *= 0.125f; q4.y *= 0.125f; q4.z *= 0.125f; q4.w *= 0.125f;
        *(float4*)&Qs[r][c4] = q4;
    }
    float m[4], l[4], o[4][4];
    #pragma unroll
    for (int i = 0; i < 4; i++) {
        m[i] = -1e30f; l[i] = 0.f;
        #pragma unroll
        for (int c = 0; c < 4; c++) o[i][c] = 0.f;
    }
    int nkt = (qt + 1) * 2;
    for (int kt = 0; kt < nkt; kt++) {
        __syncthreads();
        int k0 = b * SEQ + kt * 32;
        #pragma unroll
        for (int i = 0; i < 2; i++) {
            int idx = tid + i * 256;
            int r = idx >> 4, c4 = (idx & 15) * 4;
            *(float4*)&Ks[r][c4] = *(const float4*)(QKV + (size_t)(k0 + r) * QKVD + 1024 + kvh * HDIM + c4);
            *(float4*)&Vs[r][c4] = *(const float4*)(QKV + (size_t)(k0 + r) * QKVD + 1280 + kvh * HDIM + c4);
        }
        __syncthreads();
        float sc[4][2];
        #pragma unroll
        for (int i = 0; i < 4; i++) { sc[i][0] = 0.f; sc[i][1] = 0.f; }
        #pragma unroll
        for (int d = 0; d < 64; d += 4) {
            float4 ka = *(const float4*)&Ks[tx * 2][d];
            float4 kb = *(const float4*)&Ks[tx * 2 + 1][d];
            #pragma unroll
            for (int i = 0; i < 4; i++) {
                float4 qv = *(const float4*)&Qs[ty * 4 + i][d];
                sc[i][0] += qv.x * ka.x + qv.y * ka.y + qv.z * ka.z + qv.w * ka.w;
                sc[i][1] += qv.x * kb.x + qv.y * kb.y + qv.z * kb.z + qv.w * kb.w;
            }
        }
        int kg0 = kt * 32 + tx * 2;
        #pragma unroll
        for (int i = 0; i < 4; i++) {
            int qrow = qt * 64 + ty * 4 + i;
            if (kg0 > qrow)     sc[i][0] = -1e30f;
            if (kg0 + 1 > qrow) sc[i][1] = -1e30f;
            float tm = fmaxf(sc[i][0], sc[i][1]);
            #pragma unroll
            for (int off = 8; off; off >>= 1) tm = fmaxf(tm, __shfl_xor_sync(0xffffffffu, tm, off));
            float mn = fmaxf(m[i], tm);
            float al = __expf(m[i] - mn);
            float p0 = __expf(sc[i][0] - mn);
            float p1 = __expf(sc[i][1] - mn);
            float rs = p0 + p1;
            #pragma unroll
            for (int off = 8; off; off >>= 1) rs += __shfl_xor_sync(0xffffffffu, rs, off);
            l[i] = l[i] * al + rs;
            m[i] = mn;
            #pragma unroll
            for (int c = 0; c < 4; c++) o[i][c] *= al;
            Ps[ty * 4 + i][tx * 2]     = p0;
            Ps[ty * 4 + i][tx * 2 + 1] = p1;
        }
        __syncthreads();
        #pragma unroll 8
        for (int k = 0; k < 32; k++) {
            float4 vv = *(const float4*)&Vs[k][tx * 4];
            #pragma unroll
            for (int i = 0; i < 4; i++) {
                float p = Ps[ty * 4 + i][k];
                o[i][0] += p * vv.x; o[i][1] += p * vv.y;
                o[i][2] += p * vv.z; o[i][3] += p * vv.w;
            }
        }
    }
    #pragma unroll
    for (int i = 0; i < 4; i++) {
        float inv = 1.f / l[i];
        int row = t0 + ty * 4 + i;
        float4 ov = make_float4(o[i][0] * inv, o[i][1] * inv, o[i][2] * inv, o[i][3] * inv);
        *(float4*)(O + (size_t)row * DMODEL + head * HDIM + tx * 4) = ov;
    }
}

// ---------------- misc small kernels ----------------
__global__ void copy_kernel(float4* __restrict__ dst, const float4* __restrict__ src, int n4) {
    int i = blockIdx.x * blockDim.x + threadIdx.x;
    if (i < n4) dst[i] = src[i];
}
__global__ void zero_kernel(float* __restrict__ p, int n) {
    int i = blockIdx.x * blockDim.x + threadIdx.x;
    if (i < n) p[i] = 0.f;
}
__global__ void tgt_kernel(const float* __restrict__ XR, const float* __restrict__ u_emb,
                           const int* __restrict__ y, float* __restrict__ tgt) {
    int row = blockIdx.x * 4 + (threadIdx.x >> 5);
    int lane = threadIdx.x & 31;
    if (row >= TT) return;
    int t = y[row];
    const float* h = XR + (size_t)row * DMODEL;
    const float* u = u_emb + (size_t)t * 512;
    float s = 0.f;
    for (int i = lane * 4; i < 512; i += 128) {
        float4 hv = *(const float4*)(h + i);
        float4 uv = *(const float4*)(u + i);
        s += hv.x * uv.x + hv.y * uv.y + hv.z * uv.z + hv.w * uv.w;
    }
    #pragma unroll
    for (int off = 16; off; off >>= 1) s += __shfl_xor_sync(0xffffffffu, s, off);
    if (lane == 0) tgt[row] = 30.f * tanhf(s * (1.f / 30.f));
}
__global__ void loss_kernel(const float* __restrict__ sumexp, const float* __restrict__ tgt,
                            float* __restrict__ out) {
    float s = 0.f;
    for (int i = threadIdx.x; i < TT; i += 256)
        s += logf(sumexp[i]) - tgt[i];
    float tot = block_sum_256(s);
    if (threadIdx.x == 0) out[0] = tot * (1.f / TT);
}

// ---------------- host orchestration ----------------
static inline void gemm_launch(const float* A, int lda, const float* W, float* C, int ldc,
                               const float* scale, float* sumexp,
                               int M, int N, int K, int mode) {
    dim3 grid((N + 127) / 128, M / 128);
    gemm_tf32_kernel<<<grid, 256>>>(A, lda, W, C, ldc, scale, sumexp, M, N, K, mode);
}

extern "C" void kernel_launch(void* const* d_in, const int* in_sizes, int n_in,
                              void* d_out, int out_size) {
    const int*   ids     = (const int*)d_in[0];
    const int*   y       = (const int*)d_in[1];
    const float* u_emb   = (const float*)d_in[2];
    const float* b_emb   = (const float*)d_in[3];
    const float* Wq      = (const float*)d_in[4];
    const float* Wk      = (const float*)d_in[5];
    const float* Wv      = (const float*)d_in[6];
    const float* Wo      = (const float*)d_in[7];
    const float* qg      = (const float*)d_in[8];
    const float* a_scale = (const float*)d_in[9];
    const float* m_scale = (const float*)d_in[10];
    const float* rm      = (const float*)d_in[11];
    const float* Wf      = (const float*)d_in[12];
    const float* Wo2     = (const float*)d_in[13];
    const float* sw      = (const float*)d_in[14];

    float *X, *X0, *XR, *SK, *QKV, *ATT, *MH, *WQKV, *COS, *SIN, *SUM, *TGT;
    cudaGetSymbolAddress((void**)&X,    g_X);
    cudaGetSymbolAddress((void**)&X0,   g_X0);
    cudaGetSymbolAddress((void**)&XR,   g_XR);
    cudaGetSymbolAddress((void**)&SK,   g_SK);
    cudaGetSymbolAddress((void**)&QKV,  g_QKV);
    cudaGetSymbolAddress((void**)&ATT,  g_ATT);
    cudaGetSymbolAddress((void**)&MH,   g_MH);
    cudaGetSymbolAddress((void**)&WQKV, g_WQKV);
    cudaGetSymbolAddress((void**)&COS,  g_COS);
    cudaGetSymbolAddress((void**)&SIN,  g_SIN);
    cudaGetSymbolAddress((void**)&SUM,  g_SUMEXP);
    cudaGetSymbolAddress((void**)&TGT,  g_TGT);

    rope_table_kernel<<<(SEQ * 32 + 255) / 256, 256>>>(COS, SIN);
    {
        int tot = LNUM * QKVD * (DMODEL / 4);
        pack_qkv_kernel<<<(tot + 255) / 256, 256>>>(Wq, Wk, Wv, (float4*)WQKV);
    }
    embed_kernel<<<TT, 256>>>(ids, u_emb, b_emb, X, X0);

    auto run_block = [&](int l, const float* skip, const float* swv) {
        mix_rmsn_kernel<<<TT, 256>>>(X, X0, XR, rm + (size_t)l * 2 * DMODEL, skip, swv);
        gemm_launch(XR, DMODEL, WQKV + (size_t)l * QKVD * DMODEL, QKV, QKVD,
                    nullptr, nullptr, TT, QKVD, DMODEL, 0);
        qkrope_kernel<<<TT * (NH + NKV) / 8, 256>>>(QKV, COS, SIN, qg + (size_t)l * NH);
        flash_kernel<<<dim3(32, 32), 256>>>(QKV, ATT);
        gemm_launch(ATT, DMODEL, Wo + (size_t)l * DMODEL * DMODEL, X, DMODEL,
                    a_scale + (size_t)l * DMODEL, nullptr, TT, DMODEL, DMODEL, 1);
        rmsn_kernel<<<TT, 256>>>(X, XR);
        gemm_launch(XR, DMODEL, Wf + (size_t)l * MLPD * DMODEL, MH, MLPD,
                    nullptr, nullptr, TT, MLPD, DMODEL, 2);
        gemm_launch(MH, MLPD, Wo2 + (size_t)l * DMODEL * MLPD, X, DMODEL,
                    m_scale + (size_t)l * DMODEL, nullptr, TT, DMODEL, MLPD, 1);
    };

    // forward pass + skip stash
    for (int i = 0; i < LNUM; i++) {
        run_block(i, nullptr, nullptr);
        copy_kernel<<<(TT * DMODEL / 4 + 255) / 256, 256>>>(
            (float4*)(SK + (size_t)i * TT * DMODEL), (const float4*)X, TT * DMODEL / 4);
    }
    // reverse pass with skips: h = h + sw[i]*sk[L-1-i]; block params j = L-1-i
    for (int i = 0; i < LNUM; i++) {
        int j = LNUM - 1 - i;
        run_block(j, SK + (size_t)j * TT * DMODEL, sw + (size_t)i * DMODEL);
    }

    // final norm + loss
    rmsn_kernel<<<TT, 256>>>(X, XR);
    zero_kernel<<<(TT + 255) / 256, 256>>>(SUM, TT);
    gemm_launch(XR, DMODEL, u_emb, nullptr, VSZ, nullptr, SUM, TT, VSZ, 512, 3);
    tgt_kernel<<<TT / 4, 128>>>(XR, u_emb, y, TGT);
    loss_kernel<<<1, 256>>>(SUM, TGT, (float*)d_out);
}

// round 6
// speedup vs baseline: 2.7326x; 1.8506x over previous
#include <cuda_runtime.h>
#include <cuda_bf16.h>
#include <math.h>
#include <stdint.h>

// ---------------- model constants ----------------
#define LNUM 6
#define DMODEL 1024
#define NH 16
#define NKV 4
#define HDIM 64
#define BATCH 2
#define SEQ 2048
#define TT (BATCH*SEQ)          // 4096 tokens
#define VSZ 50257
#define HSZ 4096
#define MLPD 3072
#define QKVD 1536               // 1024 + 256 + 256
#define EPSF 1.1920929e-07f

typedef __nv_bfloat16 bf16;
typedef __nv_bfloat162 bf162;

// ---------------- scratch (device globals; no allocation allowed) ----------------
__device__ float g_X[TT*DMODEL];
__device__ float g_X0[TT*DMODEL];
__device__ float g_QKV[TT*QKVD];
__device__ float g_SK[LNUM*TT*DMODEL];
__device__ float g_COS[SEQ*32];
__device__ float g_SIN[SEQ*32];
__device__ float g_SUMEXP[TT];
__device__ float g_TGT[TT];
__device__ bf16  g_XRh[TT*DMODEL];
__device__ bf16  g_MHh[TT*MLPD];
__device__ bf16  g_ATTh[TT*DMODEL];
__device__ bf16  g_WQKVh[(size_t)LNUM*QKVD*DMODEL];
__device__ bf16  g_WOh[(size_t)LNUM*DMODEL*DMODEL];
__device__ bf16  g_WFh[(size_t)LNUM*MLPD*DMODEL];
__device__ bf16  g_WO2h[(size_t)LNUM*DMODEL*MLPD];
__device__ bf16  g_UEh[(size_t)VSZ*512];

// ---------------- helpers ----------------
__device__ __forceinline__ float block_sum_256(float v) {
    __shared__ float sh[8];
    #pragma unroll
    for (int o = 16; o; o >>= 1) v += __shfl_xor_sync(0xffffffffu, v, o);
    if ((threadIdx.x & 31) == 0) sh[threadIdx.x >> 5] = v;
    __syncthreads();
    if (threadIdx.x == 0) {
        float s = 0.f;
        #pragma unroll
        for (int i = 0; i < 8; i++) s += sh[i];
        sh[0] = s;
    }
    __syncthreads();
    return sh[0];
}

__device__ __forceinline__ void mma_bf16(float* c, uint32_t a0, uint32_t a1,
                                         uint32_t a2, uint32_t a3,
                                         uint32_t b0, uint32_t b1) {
    asm volatile(
        "mma.sync.aligned.m16n8k16.row.col.f32.bf16.bf16.f32 "
        "{%0,%1,%2,%3}, {%4,%5,%6,%7}, {%8,%9}, {%0,%1,%2,%3};"
        : "+f"(c[0]), "+f"(c[1]), "+f"(c[2]), "+f"(c[3])
        : "r"(a0), "r"(a1), "r"(a2), "r"(a3), "r"(b0), "r"(b1));
}

__device__ __forceinline__ uint4 ldsm4(uint32_t addr) {
    uint4 r;
    asm volatile("ldmatrix.sync.aligned.m8n8.x4.shared.b16 {%0,%1,%2,%3}, [%4];"
        : "=r"(r.x), "=r"(r.y), "=r"(r.z), "=r"(r.w) : "r"(addr));
    return r;
}

#define CP16(dst, src) asm volatile("cp.async.cg.shared.global [%0], [%1], 16;" :: "r"(dst), "l"(src))
#define CP_COMMIT()    asm volatile("cp.async.commit_group;")
#define CP_WAIT1()     asm volatile("cp.async.wait_group 1;")

// ---------------- rope tables ----------------
__global__ void rope_table_kernel(float* __restrict__ cosT, float* __restrict__ sinT) {
    int idx = blockIdx.x * 256 + threadIdx.x;
    if (idx >= SEQ * 32) return;
    int t = idx >> 5, j = idx & 31;
    double f = pow(10000.0, -(double)j / 32.0);
    double a = (double)t * f;
    cosT[idx] = (float)cos(a);
    sinT[idx] = (float)sin(a);
}

// ---------------- fp32 -> bf16 weight convert ----------------
__global__ void f2h_kernel(const float4* __restrict__ src, bf162* __restrict__ dst, int n4) {
    int i = blockIdx.x * 256 + threadIdx.x;
    if (i >= n4) return;
    float4 v = src[i];
    dst[2 * i]     = __floats2bfloat162_rn(v.x, v.y);
    dst[2 * i + 1] = __floats2bfloat162_rn(v.z, v.w);
}

// ---------------- pack Wq/Wk/Wv -> bf16 WQKV[l][1536][1024] ----------------
__global__ void pack_qkv_kernel(const float* __restrict__ Wq, const float* __restrict__ Wk,
                                const float* __restrict__ Wv, bf162* __restrict__ out) {
    const int ROWF4 = DMODEL / 4;
    const int TOT = LNUM * QKVD * ROWF4;
    int i = blockIdx.x * 256 + threadIdx.x;
    if (i >= TOT) return;
    int rowg = i / ROWF4, c = i % ROWF4;
    int l = rowg / QKVD, r = rowg % QKVD;
    const float4* src;
    if (r < 1024)      src = (const float4*)(Wq + ((size_t)l * 1024 + r) * DMODEL);
    else if (r < 1280) src = (const float4*)(Wk + ((size_t)l * 256 + (r - 1024)) * DMODEL);
    else               src = (const float4*)(Wv + ((size_t)l * 256 + (r - 1280)) * DMODEL);
    float4 v = src[c];
    out[2 * i]     = __floats2bfloat162_rn(v.x, v.y);
    out[2 * i + 1] = __floats2bfloat162_rn(v.z, v.w);
}

// ---------------- embedding + rmsnorm ----------------
__global__ void embed_kernel(const int* __restrict__ ids, const float* __restrict__ u_emb,
                             const float* __restrict__ b_emb,
                             float* __restrict__ X, float* __restrict__ X0) {
    int t = blockIdx.x;
    int s = t & (SEQ - 1);
    int id = ids[t];
    int pi = (s == 0) ? 0 : ids[t - 1];
    int bi = ((pi % HSZ) * (VSZ % HSZ) % HSZ + id % HSZ) % HSZ;
    int tid = threadIdx.x;
    float v[4];
    float ssq = 0.f;
    #pragma unroll
    for (int i = 0; i < 4; i++) {
        int d = i * 256 + tid;
        float x = (d < 512) ? u_emb[(size_t)id * 512 + d] : b_emb[(size_t)bi * 512 + (d - 512)];
        v[i] = x; ssq += x * x;
    }
    float tot = block_sum_256(ssq);
    float r = rsqrtf(tot * (1.f / DMODEL) + EPSF);
    #pragma unroll
    for (int i = 0; i < 4; i++) {
        int d = i * 256 + tid;
        float o = v[i] * r;
        X[(size_t)t * DMODEL + d] = o;
        X0[(size_t)t * DMODEL + d] = o;
    }
}

// ---------------- residual mix (+optional skip) then rmsnorm -> bf16 ----------------
__global__ void mix_rmsn_kernel(float* __restrict__ X, const float* __restrict__ X0,
                                bf16* __restrict__ XR, const float* __restrict__ rm,
                                const float* __restrict__ skip, const float* __restrict__ sw) {
    int t = blockIdx.x, tid = threadIdx.x;
    float v[4]; float ssq = 0.f;
    #pragma unroll
    for (int i = 0; i < 4; i++) {
        int d = i * 256 + tid;
        size_t off = (size_t)t * DMODEL + d;
        float x = X[off];
        if (skip) x += sw[d] * skip[off];
        x = rm[d] * x + rm[DMODEL + d] * X0[off];
        v[i] = x; ssq += x * x;
    }
    float tot = block_sum_256(ssq);
    float r = rsqrtf(tot * (1.f / DMODEL) + EPSF);
    #pragma unroll
    for (int i = 0; i < 4; i++) {
        int d = i * 256 + tid;
        size_t off = (size_t)t * DMODEL + d;
        X[off] = v[i];
        XR[off] = __float2bfloat16(v[i] * r);
    }
}

// ---------------- plain rmsnorm -> bf16 ----------------
__global__ void rmsn_kernel(const float* __restrict__ X, bf16* __restrict__ XR) {
    int t = blockIdx.x, tid = threadIdx.x;
    float v[4]; float ssq = 0.f;
    #pragma unroll
    for (int i = 0; i < 4; i++) {
        int d = i * 256 + tid;
        v[i] = X[(size_t)t * DMODEL + d];
        ssq += v[i] * v[i];
    }
    float tot = block_sum_256(ssq);
    float r = rsqrtf(tot * (1.f / DMODEL) + EPSF);
    #pragma unroll
    for (int i = 0; i < 4; i++) {
        int d = i * 256 + tid;
        XR[(size_t)t * DMODEL + d] = __float2bfloat16(v[i] * r);
    }
}

// ---------------- per-head rmsnorm + rope (+qg for q), QKV packed layout ----------------
__global__ void qkrope_kernel(float* __restrict__ QKV,
                              const float* __restrict__ cosT, const float* __restrict__ sinT,
                              const float* __restrict__ qg) {
    int gw = blockIdx.x * 8 + (threadIdx.x >> 5);
    int lane = threadIdx.x & 31;
    const int NQ = TT * NH;
    float* base; float gain; int t;
    if (gw < NQ) {
        t = gw >> 4; int h = gw & 15;
        base = QKV + (size_t)t * QKVD + h * HDIM;
        gain = qg[h];
    } else {
        int g2 = gw - NQ;
        if (g2 >= TT * NKV) return;
        t = g2 >> 2; int h = g2 & 3;
        base = QKV + (size_t)t * QKVD + 1024 + h * HDIM;
        gain = 1.f;
    }
    int s = t & (SEQ - 1);
    float v1 = base[lane], v2 = base[lane + 32];
    float ssq = v1 * v1 + v2 * v2;
    #pragma unroll
    for (int off = 16; off; off >>= 1) ssq += __shfl_xor_sync(0xffffffffu, ssq, off);
    float r = rsqrtf(ssq * (1.f / HDIM) + EPSF);
    v1 *= r; v2 *= r;
    float c = cosT[s * 32 + lane], sn = sinT[s * 32 + lane];
    float o1 = v1 * c + v2 * sn;
    float o2 = -v1 * sn + v2 * c;
    base[lane] = o1 * gain;
    base[lane + 32] = o2 * gain;
}

// ---------------- BF16 tensor-core GEMM: C[M,N] = A[M,K(lda)] @ W[N,K]^T ----------------
// Block 128x128, BK=32, 8 warps (warp tile 32x64), mma.m16n8k16.bf16,
// cp.async double-buffered smem, ldmatrix fragment loads.
// mode 0: Cf = acc (fp32)      mode 1: Cf += scale[n]*acc (in-place fp32)
// mode 2: Ch = relu(acc)^2 (bf16)
// mode 3: atomicAdd(sumexp[m], sum_n exp(30*tanh(acc/30)))
#define AS_STRIDE 40            // halves per smem row (80B; conflict-free ldmatrix)
#define ABUF (128*AS_STRIDE)    // halves per buffer
__global__ void __launch_bounds__(256) gemm_bf16_kernel(
    const bf16* __restrict__ A, int lda, const bf16* __restrict__ W,
    float* __restrict__ Cf, bf16* __restrict__ Ch, int ldc,
    const float* __restrict__ scale, float* __restrict__ sumexp,
    int M, int N, int K, int mode)
{
    __shared__ __align__(16) bf16 As[2*ABUF];
    __shared__ __align__(16) bf16 Bs[2*ABUF];

    int tid = threadIdx.x;
    int lane = tid & 31, wid = tid >> 5;
    int wm = wid & 3, wn = wid >> 2;       // warp tile: rows wm*32, cols wn*64
    int m0 = blockIdx.y * 128, n0 = blockIdx.x * 128;

    // cp.async assignment: thread -> row tid>>1, halves (tid&1)*16 .. +15 (two 16B chunks)
    int arow = tid >> 1;
    int ac8 = (tid & 1) * 16;
    const bf16* ApA = A + (size_t)(m0 + arow) * lda + ac8;
    int wrow = n0 + arow;
    int wsafe = (wrow < N) ? wrow : (N - 1);
    const bf16* ApW = W + (size_t)wsafe * K + ac8;
    uint32_t sA = (uint32_t)__cvta_generic_to_shared(&As[0]);
    uint32_t sB = (uint32_t)__cvta_generic_to_shared(&Bs[0]);
    uint32_t dA = sA + (uint32_t)(arow * AS_STRIDE + ac8) * 2;
    uint32_t dB = sB + (uint32_t)(arow * AS_STRIDE + ac8) * 2;

    // ldmatrix per-lane offsets
    int tIdx = lane >> 3, rIn = lane & 7;
    int aRow = wm * 32 + (tIdx & 1) * 8 + rIn;       // + i*16
    int kCol = (tIdx >> 1) * 8;                       // + s*16
    uint32_t aOff[2][2], bOff[4][2];
    #pragma unroll
    for (int i = 0; i < 2; i++)
        #pragma unroll
        for (int s = 0; s < 2; s++)
            aOff[i][s] = (uint32_t)(((aRow + i * 16) * AS_STRIDE) + kCol + s * 16) * 2;
    #pragma unroll
    for (int jj = 0; jj < 4; jj++)
        #pragma unroll
        for (int s = 0; s < 2; s++)
            bOff[jj][s] = (uint32_t)(((wn * 64 + jj * 16 + (tIdx & 1) * 8 + rIn) * AS_STRIDE) + kCol + s * 16) * 2;

    float acc[2][8][4];
    #pragma unroll
    for (int i = 0; i < 2; i++)
        #pragma unroll
        for (int j = 0; j < 8; j++)
            #pragma unroll
            for (int c = 0; c < 4; c++) acc[i][j][c] = 0.f;

    int nk = K >> 5;
    // prologue: tile 0 -> buffer 0  (each thread: 2x16B = halves ac8..ac8+15)
    {
        CP16(dA, ApA); CP16(dA + 16, ApA + 8);
        CP16(dB, ApW); CP16(dB + 16, ApW + 8);
        CP_COMMIT();
    }
    int buf = 0;
    for (int kt = 0; kt < nk; kt++) {
        // issue next tile into other buffer
        if (kt + 1 < nk) {
            int k0 = (kt + 1) << 5;
            uint32_t bo = (buf ^ 1) * (ABUF * 2);
            CP16(dA + bo, ApA + k0); CP16(dA + bo + 16, ApA + k0 + 8);
            CP16(dB + bo, ApW + k0); CP16(dB + bo + 16, ApW + k0 + 8);
        }
        CP_COMMIT();
        CP_WAIT1();
        __syncthreads();

        uint32_t bA = sA + buf * (ABUF * 2);
        uint32_t bB = sB + buf * (ABUF * 2);
        #pragma unroll
        for (int s = 0; s < 2; s++) {
            uint4 af0 = ldsm4(bA + aOff[0][s]);
            uint4 af1 = ldsm4(bA + aOff[1][s]);
            #pragma unroll
            for (int jj = 0; jj < 4; jj++) {
                uint4 bf = ldsm4(bB + bOff[jj][s]);
                mma_bf16(acc[0][2 * jj],     af0.x, af0.y, af0.z, af0.w, bf.x, bf.z);
                mma_bf16(acc[0][2 * jj + 1], af0.x, af0.y, af0.z, af0.w, bf.y, bf.w);
                mma_bf16(acc[1][2 * jj],     af1.x, af1.y, af1.z, af1.w, bf.x, bf.z);
                mma_bf16(acc[1][2 * jj + 1], af1.x, af1.y, af1.z, af1.w, bf.y, bf.w);
            }
        }
        __syncthreads();
        buf ^= 1;
    }

    int r0 = lane >> 2, c0v = (lane & 3) * 2;

    if (mode == 3) {
        #pragma unroll
        for (int i = 0; i < 2; i++) {
            #pragma unroll
            for (int h = 0; h < 2; h++) {
                float s = 0.f;
                #pragma unroll
                for (int j = 0; j < 8; j++) {
                    int col = n0 + (8 * wn + j) * 8 + c0v;
                    if (col < N)     s += __expf(30.f * tanhf(acc[i][j][h * 2 + 0] * (1.f / 30.f)));
                    if (col + 1 < N) s += __expf(30.f * tanhf(acc[i][j][h * 2 + 1] * (1.f / 30.f)));
                }
                s += __shfl_xor_sync(0xffffffffu, s, 1);
                s += __shfl_xor_sync(0xffffffffu, s, 2);
                if ((lane & 3) == 0) {
                    int row = m0 + (2 * wm + i) * 16 + r0 + h * 8;
                    atomicAdd(&sumexp[row], s);
                }
            }
        }
        return;
    }

    #pragma unroll
    for (int i = 0; i < 2; i++) {
        int mrow = m0 + (2 * wm + i) * 16 + r0;
        #pragma unroll
        for (int j = 0; j < 8; j++) {
            int col = n0 + (8 * wn + j) * 8 + c0v;
            if (mode == 0) {
                float* p0 = Cf + (size_t)mrow * ldc + col;
                float* p1 = p0 + (size_t)8 * ldc;
                *(float2*)p0 = make_float2(acc[i][j][0], acc[i][j][1]);
                *(float2*)p1 = make_float2(acc[i][j][2], acc[i][j][3]);
            } else if (mode == 1) {
                float* p0 = Cf + (size_t)mrow * ldc + col;
                float* p1 = p0 + (size_t)8 * ldc;
                float2 sc = *(const float2*)(scale + col);
                float2 v0 = *(const float2*)p0;
                float2 v1 = *(const float2*)p1;
                v0.x += sc.x * acc[i][j][0]; v0.y += sc.y * acc[i][j][1];
                v1.x += sc.x * acc[i][j][2]; v1.y += sc.y * acc[i][j][3];
                *(float2*)p0 = v0; *(float2*)p1 = v1;
            } else { // mode 2: relu^2 -> bf16
                bf16* p0 = Ch + (size_t)mrow * ldc + col;
                bf16* p1 = p0 + (size_t)8 * ldc;
                float a = fmaxf(acc[i][j][0], 0.f), b = fmaxf(acc[i][j][1], 0.f);
                float c = fmaxf(acc[i][j][2], 0.f), d = fmaxf(acc[i][j][3], 0.f);
                *(bf162*)p0 = __floats2bfloat162_rn(a * a, b * b);
                *(bf162*)p1 = __floats2bfloat162_rn(c * c, d * d);
            }
        }
    }
}

// ---------------- causal flash attention (fp32, GQA), packed QKV -> bf16 out ----------------
__global__ void __launch_bounds__(256) flash_kernel(
    const float* __restrict__ QKV, bf16* __restrict__ O)
{
    __shared__ float Qs[64][64];
    __shared__ float Ks[32][68];
    __shared__ float Vs[32][68];
    __shared__ float Ps[64][33];
    int qt = blockIdx.x;
    int bh = blockIdx.y;
    int b = bh >> 4, head = bh & 15, kvh = head >> 2;
    int tid = threadIdx.x, tx = tid & 15, ty = tid >> 4;
    int t0 = b * SEQ + qt * 64;
    #pragma unroll
    for (int i = 0; i < 4; i++) {
        int idx = tid + i * 256;
        int r = idx >> 4, c4 = (idx & 15) * 4;
        float4 q4 = *(const float4*)(QKV + (size_t)(t0 + r) * QKVD + head * HDIM + c4);
        q4.x *= 0.125f; q4.y *= 0.125f; q4.z *= 0.125f; q4.w *= 0.125f;
        *(float4*)&Qs[r][c4] = q4;
    }
    float m[4], l[4], o[4][4];
    #pragma unroll
    for (int i = 0; i < 4; i++) {
        m[i] = -1e30f; l[i] = 0.f;
        #pragma unroll
        for (int c = 0; c < 4; c++) o[i][c] = 0.f;
    }
    int nkt = (qt + 1) * 2;
    for (int kt = 0; kt < nkt; kt++) {
        __syncthreads();
        int k0 = b * SEQ + kt * 32;
        #pragma unroll
        for (int i = 0; i < 2; i++) {
            int idx = tid + i * 256;
            int r = idx >> 4, c4 = (idx & 15) * 4;
            *(float4*)&Ks[r][c4] = *(const float4*)(QKV + (size_t)(k0 + r) * QKVD + 1024 + kvh * HDIM + c4);
            *(float4*)&Vs[r][c4] = *(const float4*)(QKV + (size_t)(k0 + r) * QKVD + 1280 + kvh * HDIM + c4);
        }
        __syncthreads();
        float sc[4][2];
        #pragma unroll
        for (int i = 0; i < 4; i++) { sc[i][0] = 0.f; sc[i][1] = 0.f; }
        #pragma unroll
        for (int d = 0; d < 64; d += 4) {
            float4 ka = *(const float4*)&Ks[tx * 2][d];
            float4 kb = *(const float4*)&Ks[tx * 2 + 1][d];
            #pragma unroll
            for (int i = 0; i < 4; i++) {
                float4 qv = *(const float4*)&Qs[ty * 4 + i][d];
                sc[i][0] += qv.x * ka.x + qv.y * ka.y + qv.z * ka.z + qv.w * ka.w;
                sc[i][1] += qv.x * kb.x + qv.y * kb.y + qv.z * kb.z + qv.w * kb.w;
            }
        }
        int kg0 = kt * 32 + tx * 2;
        #pragma unroll
        for (int i = 0; i < 4; i++) {
            int qrow = qt * 64 + ty * 4 + i;
            if (kg0 > qrow)     sc[i][0] = -1e30f;
            if (kg0 + 1 > qrow) sc[i][1] = -1e30f;
            float tm = fmaxf(sc[i][0], sc[i][1]);
            #pragma unroll
            for (int off = 8; off; off >>= 1) tm = fmaxf(tm, __shfl_xor_sync(0xffffffffu, tm, off));
            float mn = fmaxf(m[i], tm);
            float al = __expf(m[i] - mn);
            float p0 = __expf(sc[i][0] - mn);
            float p1 = __expf(sc[i][1] - mn);
            float rs = p0 + p1;
            #pragma unroll
            for (int off = 8; off; off >>= 1) rs += __shfl_xor_sync(0xffffffffu, rs, off);
            l[i] = l[i] * al + rs;
            m[i] = mn;
            #pragma unroll
            for (int c = 0; c < 4; c++) o[i][c] *= al;
            Ps[ty * 4 + i][tx * 2]     = p0;
            Ps[ty * 4 + i][tx * 2 + 1] = p1;
        }
        __syncthreads();
        #pragma unroll 8
        for (int k = 0; k < 32; k++) {
            float4 vv = *(const float4*)&Vs[k][tx * 4];
            #pragma unroll
            for (int i = 0; i < 4; i++) {
                float p = Ps[ty * 4 + i][k];
                o[i][0] += p * vv.x; o[i][1] += p * vv.y;
                o[i][2] += p * vv.z; o[i][3] += p * vv.w;
            }
        }
    }
    #pragma unroll
    for (int i = 0; i < 4; i++) {
        float inv = 1.f / l[i];
        int row = t0 + ty * 4 + i;
        bf16* p = O + (size_t)row * DMODEL + head * HDIM + tx * 4;
        *(bf162*)p       = __floats2bfloat162_rn(o[i][0] * inv, o[i][1] * inv);
        *(bf162*)(p + 2) = __floats2bfloat162_rn(o[i][2] * inv, o[i][3] * inv);
    }
}

// ---------------- misc small kernels ----------------
__global__ void copy_kernel(float4* __restrict__ dst, const float4* __restrict__ src, int n4) {
    int i = blockIdx.x * blockDim.x + threadIdx.x;
    if (i < n4) dst[i] = src[i];
}
__global__ void zero_kernel(float* __restrict__ p, int n) {
    int i = blockIdx.x * blockDim.x + threadIdx.x;
    if (i < n) p[i] = 0.f;
}
__global__ void tgt_kernel(const bf16* __restrict__ XR, const float* __restrict__ u_emb,
                           const int* __restrict__ y, float* __restrict__ tgt) {
    int row = blockIdx.x * 4 + (threadIdx.x >> 5);
    int lane = threadIdx.x & 31;
    if (row >= TT) return;
    int t = y[row];
    const bf16* h = XR + (size_t)row * DMODEL;
    const float* u = u_emb + (size_t)t * 512;
    float s = 0.f;
    for (int i = lane * 4; i < 512; i += 128) {
        bf162 h0 = *(const bf162*)(h + i);
        bf162 h1 = *(const bf162*)(h + i + 2);
        float4 uv = *(const float4*)(u + i);
        s += __bfloat162float(h0.x) * uv.x + __bfloat162float(h0.y) * uv.y
           + __bfloat162float(h1.x) * uv.z + __bfloat162float(h1.y) * uv.w;
    }
    #pragma unroll
    for (int off = 16; off; off >>= 1) s += __shfl_xor_sync(0xffffffffu, s, off);
    if (lane == 0) tgt[row] = 30.f * tanhf(s * (1.f / 30.f));
}
__global__ void loss_kernel(const float* __restrict__ sumexp, const float* __restrict__ tgt,
                            float* __restrict__ out) {
    float s = 0.f;
    for (int i = threadIdx.x; i < TT; i += 256)
        s += logf(sumexp[i]) - tgt[i];
    float tot = block_sum_256(s);
    if (threadIdx.x == 0) out[0] = tot * (1.f / TT);
}

// ---------------- host orchestration ----------------
static inline void gemm_launch(const bf16* A, int lda, const bf16* W,
                               float* Cf, bf16* Ch, int ldc,
                               const float* scale, float* sumexp,
                               int M, int N, int K, int mode) {
    dim3 grid((N + 127) / 128, M / 128);
    gemm_bf16_kernel<<<grid, 256>>>(A, lda, W, Cf, Ch, ldc, scale, sumexp, M, N, K, mode);
}

extern "C" void kernel_launch(void* const* d_in, const int* in_sizes, int n_in,
                              void* d_out, int out_size) {
    const int*   ids     = (const int*)d_in[0];
    const int*   y       = (const int*)d_in[1];
    const float* u_emb   = (const float*)d_in[2];
    const float* b_emb   = (const float*)d_in[3];
    const float* Wq      = (const float*)d_in[4];
    const float* Wk      = (const float*)d_in[5];
    const float* Wv      = (const float*)d_in[6];
    const float* Wo      = (const float*)d_in[7];
    const float* qg      = (const float*)d_in[8];
    const float* a_scale = (const float*)d_in[9];
    const float* m_scale = (const float*)d_in[10];
    const float* rm      = (const float*)d_in[11];
    const float* Wf      = (const float*)d_in[12];
    const float* Wo2     = (const float*)d_in[13];
    const float* sw      = (const float*)d_in[14];

    float *X, *X0, *QKV, *SK, *COS, *SIN, *SUM, *TGT;
    bf16 *XRh, *MHh, *ATTh, *WQKVh, *WOh, *WFh, *WO2h, *UEh;
    cudaGetSymbolAddress((void**)&X,     g_X);
    cudaGetSymbolAddress((void**)&X0,    g_X0);
    cudaGetSymbolAddress((void**)&QKV,   g_QKV);
    cudaGetSymbolAddress((void**)&SK,    g_SK);
    cudaGetSymbolAddress((void**)&COS,   g_COS);
    cudaGetSymbolAddress((void**)&SIN,   g_SIN);
    cudaGetSymbolAddress((void**)&SUM,   g_SUMEXP);
    cudaGetSymbolAddress((void**)&TGT,   g_TGT);
    cudaGetSymbolAddress((void**)&XRh,   g_XRh);
    cudaGetSymbolAddress((void**)&MHh,   g_MHh);
    cudaGetSymbolAddress((void**)&ATTh,  g_ATTh);
    cudaGetSymbolAddress((void**)&WQKVh, g_WQKVh);
    cudaGetSymbolAddress((void**)&WOh,   g_WOh);
    cudaGetSymbolAddress((void**)&WFh,   g_WFh);
    cudaGetSymbolAddress((void**)&WO2h,  g_WO2h);
    cudaGetSymbolAddress((void**)&UEh,   g_UEh);

    rope_table_kernel<<<(SEQ * 32 + 255) / 256, 256>>>(COS, SIN);
    {
        int tot = LNUM * QKVD * (DMODEL / 4);
        pack_qkv_kernel<<<(tot + 255) / 256, 256>>>(Wq, Wk, Wv, (bf162*)WQKVh);
        int n4;
        n4 = LNUM * DMODEL * DMODEL / 4;
        f2h_kernel<<<(n4 + 255) / 256, 256>>>((const float4*)Wo, (bf162*)WOh, n4);
        n4 = LNUM * MLPD * DMODEL / 4;
        f2h_kernel<<<(n4 + 255) / 256, 256>>>((const float4*)Wf, (bf162*)WFh, n4);
        f2h_kernel<<<(n4 + 255) / 256, 256>>>((const float4*)Wo2, (bf162*)WO2h, n4);
        n4 = VSZ * 512 / 4;
        f2h_kernel<<<(n4 + 255) / 256, 256>>>((const float4*)u_emb, (bf162*)UEh, n4);
    }
    embed_kernel<<<TT, 256>>>(ids, u_emb, b_emb, X, X0);

    auto run_block = [&](int l, const float* skip, const float* swv) {
        mix_rmsn_kernel<<<TT, 256>>>(X, X0, XRh, rm + (size_t)l * 2 * DMODEL, skip, swv);
        gemm_launch(XRh, DMODEL, WQKVh + (size_t)l * QKVD * DMODEL, QKV, nullptr, QKVD,
                    nullptr, nullptr, TT, QKVD, DMODEL, 0);
        qkrope_kernel<<<TT * (NH + NKV) / 8, 256>>>(QKV, COS, SIN, qg + (size_t)l * NH);
        flash_kernel<<<dim3(32, 32), 256>>>(QKV, ATTh);
        gemm_launch(ATTh, DMODEL, WOh + (size_t)l * DMODEL * DMODEL, X, nullptr, DMODEL,
                    a_scale + (size_t)l * DMODEL, nullptr, TT, DMODEL, DMODEL, 1);
        rmsn_kernel<<<TT, 256>>>(X, XRh);
        gemm_launch(XRh, DMODEL, WFh + (size_t)l * MLPD * DMODEL, nullptr, MHh, MLPD,
                    nullptr, nullptr, TT, MLPD, DMODEL, 2);
        gemm_launch(MHh, MLPD, WO2h + (size_t)l * DMODEL * MLPD, X, nullptr, DMODEL,
                    m_scale + (size_t)l * DMODEL, nullptr, TT, DMODEL, MLPD, 1);
    };

    // forward pass + skip stash
    for (int i = 0; i < LNUM; i++) {
        run_block(i, nullptr, nullptr);
        copy_kernel<<<(TT * DMODEL / 4 + 255) / 256, 256>>>(
            (float4*)(SK + (size_t)i * TT * DMODEL), (const float4*)X, TT * DMODEL / 4);
    }
    // reverse pass with skips: h = h + sw[i]*sk[L-1-i]; block params j = L-1-i
    for (int i = 0; i < LNUM; i++) {
        int j = LNUM - 1 - i;
        run_block(j, SK + (size_t)j * TT * DMODEL, sw + (size_t)i * DMODEL);
    }

    // final norm + loss
    rmsn_kernel<<<TT, 256>>>(X, XRh);
    zero_kernel<<<(TT + 255) / 256, 256>>>(SUM, TT);
    gemm_launch(XRh, DMODEL, UEh, nullptr, nullptr, VSZ, nullptr, SUM, TT, VSZ, 512, 3);
    tgt_kernel<<<TT / 4, 128>>>(XRh, u_emb, y, TGT);
    loss_kernel<<<1, 256>>>(SUM, TGT, (float*)d_out);
}

// round 7
// speedup vs baseline: 6.3279x; 2.3157x over previous
#include <cuda_runtime.h>
#include <cuda_bf16.h>
#include <math.h>
#include <stdint.h>

// ---------------- model constants ----------------
#define LNUM 6
#define DMODEL 1024
#define NH 16
#define NKV 4
#define HDIM 64
#define BATCH 2
#define SEQ 2048
#define TT (BATCH*SEQ)          // 4096 tokens
#define VSZ 50257
#define HSZ 4096
#define MLPD 3072
#define QKVD 1536               // 1024 + 256 + 256
#define EPSF 1.1920929e-07f

typedef __nv_bfloat16 bf16;
typedef __nv_bfloat162 bf162;

// ---------------- scratch (device globals; no allocation allowed) ----------------
__device__ float g_X[TT*DMODEL];
__device__ float g_X0[TT*DMODEL];
__device__ float g_QKV[TT*QKVD];
__device__ float g_SK[LNUM*TT*DMODEL];
__device__ float g_COS[SEQ*32];
__device__ float g_SIN[SEQ*32];
__device__ float g_SUMEXP[TT];
__device__ float g_TGT[TT];
__device__ bf16  g_XRh[TT*DMODEL];
__device__ bf16  g_MHh[TT*MLPD];
__device__ bf16  g_ATTh[TT*DMODEL];
__device__ bf16  g_Qh[TT*NH*HDIM];
__device__ bf16  g_Kh[TT*NKV*HDIM];
__device__ bf16  g_Vh[TT*NKV*HDIM];
__device__ bf16  g_WQKVh[(size_t)LNUM*QKVD*DMODEL];
__device__ bf16  g_WOh[(size_t)LNUM*DMODEL*DMODEL];
__device__ bf16  g_WFh[(size_t)LNUM*MLPD*DMODEL];
__device__ bf16  g_WO2h[(size_t)LNUM*DMODEL*MLPD];
__device__ bf16  g_UEh[(size_t)VSZ*512];

// ---------------- helpers ----------------
__device__ __forceinline__ float block_sum_256(float v) {
    __shared__ float sh[8];
    #pragma unroll
    for (int o = 16; o; o >>= 1) v += __shfl_xor_sync(0xffffffffu, v, o);
    if ((threadIdx.x & 31) == 0) sh[threadIdx.x >> 5] = v;
    __syncthreads();
    if (threadIdx.x == 0) {
        float s = 0.f;
        #pragma unroll
        for (int i = 0; i < 8; i++) s += sh[i];
        sh[0] = s;
    }
    __syncthreads();
    return sh[0];
}

__device__ __forceinline__ void mma_bf16(float* c, uint32_t a0, uint32_t a1,
                                         uint32_t a2, uint32_t a3,
                                         uint32_t b0, uint32_t b1) {
    asm volatile(
        "mma.sync.aligned.m16n8k16.row.col.f32.bf16.bf16.f32 "
        "{%0,%1,%2,%3}, {%4,%5,%6,%7}, {%8,%9}, {%0,%1,%2,%3};"
        : "+f"(c[0]), "+f"(c[1]), "+f"(c[2]), "+f"(c[3])
        : "r"(a0), "r"(a1), "r"(a2), "r"(a3), "r"(b0), "r"(b1));
}

__device__ __forceinline__ uint4 ldsm4(uint32_t addr) {
    uint4 r;
    asm volatile("ldmatrix.sync.aligned.m8n8.x4.shared.b16 {%0,%1,%2,%3}, [%4];"
        : "=r"(r.x), "=r"(r.y), "=r"(r.z), "=r"(r.w) : "r"(addr));
    return r;
}
__device__ __forceinline__ uint4 ldsm4t(uint32_t addr) {
    uint4 r;
    asm volatile("ldmatrix.sync.aligned.m8n8.x4.trans.shared.b16 {%0,%1,%2,%3}, [%4];"
        : "=r"(r.x), "=r"(r.y), "=r"(r.z), "=r"(r.w) : "r"(addr));
    return r;
}
__device__ __forceinline__ uint32_t packbf(float x, float y) {
    bf162 r = __floats2bfloat162_rn(x, y);
    return *(uint32_t*)&r;
}

#define CP16(dst, src) asm volatile("cp.async.cg.shared.global [%0], [%1], 16;" :: "r"(dst), "l"(src))
#define CP_COMMIT()    asm volatile("cp.async.commit_group;")
#define CP_WAIT1()     asm volatile("cp.async.wait_group 1;")

// ---------------- rope tables ----------------
__global__ void rope_table_kernel(float* __restrict__ cosT, float* __restrict__ sinT) {
    int idx = blockIdx.x * 256 + threadIdx.x;
    if (idx >= SEQ * 32) return;
    int t = idx >> 5, j = idx & 31;
    double f = pow(10000.0, -(double)j / 32.0);
    double a = (double)t * f;
    cosT[idx] = (float)cos(a);
    sinT[idx] = (float)sin(a);
}

// ---------------- fp32 -> bf16 weight convert ----------------
__global__ void f2h_kernel(const float4* __restrict__ src, bf162* __restrict__ dst, int n4) {
    int i = blockIdx.x * 256 + threadIdx.x;
    if (i >= n4) return;
    float4 v = src[i];
    dst[2 * i]     = __floats2bfloat162_rn(v.x, v.y);
    dst[2 * i + 1] = __floats2bfloat162_rn(v.z, v.w);
}

// ---------------- pack Wq/Wk/Wv -> bf16 WQKV[l][1536][1024] ----------------
__global__ void pack_qkv_kernel(const float* __restrict__ Wq, const float* __restrict__ Wk,
                                const float* __restrict__ Wv, bf162* __restrict__ out) {
    const int ROWF4 = DMODEL / 4;
    const int TOT = LNUM * QKVD * ROWF4;
    int i = blockIdx.x * 256 + threadIdx.x;
    if (i >= TOT) return;
    int rowg = i / ROWF4, c = i % ROWF4;
    int l = rowg / QKVD, r = rowg % QKVD;
    const float4* src;
    if (r < 1024)      src = (const float4*)(Wq + ((size_t)l * 1024 + r) * DMODEL);
    else if (r < 1280) src = (const float4*)(Wk + ((size_t)l * 256 + (r - 1024)) * DMODEL);
    else               src = (const float4*)(Wv + ((size_t)l * 256 + (r - 1280)) * DMODEL);
    float4 v = src[c];
    out[2 * i]     = __floats2bfloat162_rn(v.x, v.y);
    out[2 * i + 1] = __floats2bfloat162_rn(v.z, v.w);
}

// ---------------- embedding + rmsnorm ----------------
__global__ void embed_kernel(const int* __restrict__ ids, const float* __restrict__ u_emb,
                             const float* __restrict__ b_emb,
                             float* __restrict__ X, float* __restrict__ X0) {
    int t = blockIdx.x;
    int s = t & (SEQ - 1);
    int id = ids[t];
    int pi = (s == 0) ? 0 : ids[t - 1];
    int bi = ((pi % HSZ) * (VSZ % HSZ) % HSZ + id % HSZ) % HSZ;
    int tid = threadIdx.x;
    float v[4];
    float ssq = 0.f;
    #pragma unroll
    for (int i = 0; i < 4; i++) {
        int d = i * 256 + tid;
        float x = (d < 512) ? u_emb[(size_t)id * 512 + d] : b_emb[(size_t)bi * 512 + (d - 512)];
        v[i] = x; ssq += x * x;
    }
    float tot = block_sum_256(ssq);
    float r = rsqrtf(tot * (1.f / DMODEL) + EPSF);
    #pragma unroll
    for (int i = 0; i < 4; i++) {
        int d = i * 256 + tid;
        float o = v[i] * r;
        X[(size_t)t * DMODEL + d] = o;
        X0[(size_t)t * DMODEL + d] = o;
    }
}

// ---------------- residual mix (+optional skip) then rmsnorm -> bf16 ----------------
__global__ void mix_rmsn_kernel(float* __restrict__ X, const float* __restrict__ X0,
                                bf16* __restrict__ XR, const float* __restrict__ rm,
                                const float* __restrict__ skip, const float* __restrict__ sw) {
    int t = blockIdx.x, tid = threadIdx.x;
    float v[4]; float ssq = 0.f;
    #pragma unroll
    for (int i = 0; i < 4; i++) {
        int d = i * 256 + tid;
        size_t off = (size_t)t * DMODEL + d;
        float x = X[off];
        if (skip) x += sw[d] * skip[off];
        x = rm[d] * x + rm[DMODEL + d] * X0[off];
        v[i] = x; ssq += x * x;
    }
    float tot = block_sum_256(ssq);
    float r = rsqrtf(tot * (1.f / DMODEL) + EPSF);
    #pragma unroll
    for (int i = 0; i < 4; i++) {
        int d = i * 256 + tid;
        size_t off = (size_t)t * DMODEL + d;
        X[off] = v[i];
        XR[off] = __float2bfloat16(v[i] * r);
    }
}

// ---------------- plain rmsnorm -> bf16 ----------------
__global__ void rmsn_kernel(const float* __restrict__ X, bf16* __restrict__ XR) {
    int t = blockIdx.x, tid = threadIdx.x;
    float v[4]; float ssq = 0.f;
    #pragma unroll
    for (int i = 0; i < 4; i++) {
        int d = i * 256 + tid;
        v[i] = X[(size_t)t * DMODEL + d];
        ssq += v[i] * v[i];
    }
    float tot = block_sum_256(ssq);
    float r = rsqrtf(tot * (1.f / DMODEL) + EPSF);
    #pragma unroll
    for (int i = 0; i < 4; i++) {
        int d = i * 256 + tid;
        XR[(size_t)t * DMODEL + d] = __float2bfloat16(v[i] * r);
    }
}

// ---------------- per-head rmsnorm + rope, fp32 QKV -> bf16 Qh/Kh/Vh ----------------
__device__ __forceinline__ void rope_norm_store(const float* __restrict__ src,
                                                bf16* __restrict__ dst, int t, int lane,
                                                float gain,
                                                const float* __restrict__ cosT,
                                                const float* __restrict__ sinT) {
    int s = t & (SEQ - 1);
    float v1 = src[lane], v2 = src[lane + 32];
    float ssq = v1 * v1 + v2 * v2;
    #pragma unroll
    for (int off = 16; off; off >>= 1) ssq += __shfl_xor_sync(0xffffffffu, ssq, off);
    float r = rsqrtf(ssq * (1.f / HDIM) + EPSF);
    v1 *= r; v2 *= r;
    float c = cosT[s * 32 + lane], sn = sinT[s * 32 + lane];
    dst[lane]      = __float2bfloat16((v1 * c + v2 * sn) * gain);
    dst[lane + 32] = __float2bfloat16((-v1 * sn + v2 * c) * gain);
}

__global__ void qkrope_kernel(const float* __restrict__ QKV,
                              bf16* __restrict__ Qh, bf16* __restrict__ Kh, bf16* __restrict__ Vh,
                              const float* __restrict__ cosT, const float* __restrict__ sinT,
                              const float* __restrict__ qg) {
    int gw = blockIdx.x * 8 + (threadIdx.x >> 5);
    int lane = threadIdx.x & 31;
    const int NQ = TT * NH, NK = TT * NKV;
    if (gw < NQ) {
        int t = gw >> 4, h = gw & 15;
        rope_norm_store(QKV + (size_t)t * QKVD + h * HDIM,
                        Qh + (size_t)t * (NH * HDIM) + h * HDIM,
                        t, lane, qg[h] * 0.125f, cosT, sinT);  // fold 1/sqrt(64)
    } else if (gw < NQ + NK) {
        int g2 = gw - NQ;
        int t = g2 >> 2, h = g2 & 3;
        rope_norm_store(QKV + (size_t)t * QKVD + 1024 + h * HDIM,
                        Kh + (size_t)t * (NKV * HDIM) + h * HDIM,
                        t, lane, 1.f, cosT, sinT);
    } else {
        int g3 = gw - NQ - NK;
        if (g3 >= TT * NKV) return;
        int t = g3 >> 2, h = g3 & 3;
        const float* src = QKV + (size_t)t * QKVD + 1280 + h * HDIM;
        bf16* dst = Vh + (size_t)t * (NKV * HDIM) + h * HDIM;
        dst[lane]      = __float2bfloat16(src[lane]);
        dst[lane + 32] = __float2bfloat16(src[lane + 32]);
    }
}

// ---------------- BF16 tensor-core GEMM: C[M,N] = A[M,K(lda)] @ W[N,K]^T ----------------
#define AS_STRIDE 40            // halves per smem row (80B; conflict-free ldmatrix)
#define ABUF (128*AS_STRIDE)    // halves per buffer
__global__ void __launch_bounds__(256) gemm_bf16_kernel(
    const bf16* __restrict__ A, int lda, const bf16* __restrict__ W,
    float* __restrict__ Cf, bf16* __restrict__ Ch, int ldc,
    const float* __restrict__ scale, float* __restrict__ sumexp,
    int M, int N, int K, int mode)
{
    __shared__ __align__(16) bf16 As[2*ABUF];
    __shared__ __align__(16) bf16 Bs[2*ABUF];

    int tid = threadIdx.x;
    int lane = tid & 31, wid = tid >> 5;
    int wm = wid & 3, wn = wid >> 2;
    int m0 = blockIdx.y * 128, n0 = blockIdx.x * 128;

    int arow = tid >> 1;
    int ac8 = (tid & 1) * 16;
    const bf16* ApA = A + (size_t)(m0 + arow) * lda + ac8;
    int wrow = n0 + arow;
    int wsafe = (wrow < N) ? wrow : (N - 1);
    const bf16* ApW = W + (size_t)wsafe * K + ac8;
    uint32_t sA = (uint32_t)__cvta_generic_to_shared(&As[0]);
    uint32_t sB = (uint32_t)__cvta_generic_to_shared(&Bs[0]);
    uint32_t dA = sA + (uint32_t)(arow * AS_STRIDE + ac8) * 2;
    uint32_t dB = sB + (uint32_t)(arow * AS_STRIDE + ac8) * 2;

    int tIdx = lane >> 3, rIn = lane & 7;
    int aRow = wm * 32 + (tIdx & 1) * 8 + rIn;
    int kCol = (tIdx >> 1) * 8;
    uint32_t aOff[2][2], bOff[4][2];
    #pragma unroll
    for (int i = 0; i < 2; i++)
        #pragma unroll
        for (int s = 0; s < 2; s++)
            aOff[i][s] = (uint32_t)(((aRow + i * 16) * AS_STRIDE) + kCol + s * 16) * 2;
    #pragma unroll
    for (int jj = 0; jj < 4; jj++)
        #pragma unroll
        for (int s = 0; s < 2; s++)
            bOff[jj][s] = (uint32_t)(((wn * 64 + jj * 16 + (tIdx & 1) * 8 + rIn) * AS_STRIDE) + kCol + s * 16) * 2;

    float acc[2][8][4];
    #pragma unroll
    for (int i = 0; i < 2; i++)
        #pragma unroll
        for (int j = 0; j < 8; j++)
            #pragma unroll
            for (int c = 0; c < 4; c++) acc[i][j][c] = 0.f;

    int nk = K >> 5;
    {
        CP16(dA, ApA); CP16(dA + 16, ApA + 8);
        CP16(dB, ApW); CP16(dB + 16, ApW + 8);
        CP_COMMIT();
    }
    int buf = 0;
    for (int kt = 0; kt < nk; kt++) {
        if (kt + 1 < nk) {
            int k0 = (kt + 1) << 5;
            uint32_t bo = (buf ^ 1) * (ABUF * 2);
            CP16(dA + bo, ApA + k0); CP16(dA + bo + 16, ApA + k0 + 8);
            CP16(dB + bo, ApW + k0); CP16(dB + bo + 16, ApW + k0 + 8);
        }
        CP_COMMIT();
        CP_WAIT1();
        __syncthreads();

        uint32_t bA = sA + buf * (ABUF * 2);
        uint32_t bB = sB + buf * (ABUF * 2);
        #pragma unroll
        for (int s = 0; s < 2; s++) {
            uint4 af0 = ldsm4(bA + aOff[0][s]);
            uint4 af1 = ldsm4(bA + aOff[1][s]);
            #pragma unroll
            for (int jj = 0; jj < 4; jj++) {
                uint4 bfr = ldsm4(bB + bOff[jj][s]);
                mma_bf16(acc[0][2 * jj],     af0.x, af0.y, af0.z, af0.w, bfr.x, bfr.z);
                mma_bf16(acc[0][2 * jj + 1], af0.x, af0.y, af0.z, af0.w, bfr.y, bfr.w);
                mma_bf16(acc[1][2 * jj],     af1.x, af1.y, af1.z, af1.w, bfr.x, bfr.z);
                mma_bf16(acc[1][2 * jj + 1], af1.x, af1.y, af1.z, af1.w, bfr.y, bfr.w);
            }
        }
        __syncthreads();
        buf ^= 1;
    }

    int r0 = lane >> 2, c0v = (lane & 3) * 2;

    if (mode == 3) {
        #pragma unroll
        for (int i = 0; i < 2; i++) {
            #pragma unroll
            for (int h = 0; h < 2; h++) {
                float s = 0.f;
                #pragma unroll
                for (int j = 0; j < 8; j++) {
                    int col = n0 + (8 * wn + j) * 8 + c0v;
                    if (col < N)     s += __expf(30.f * tanhf(acc[i][j][h * 2 + 0] * (1.f / 30.f)));
                    if (col + 1 < N) s += __expf(30.f * tanhf(acc[i][j][h * 2 + 1] * (1.f / 30.f)));
                }
                s += __shfl_xor_sync(0xffffffffu, s, 1);
                s += __shfl_xor_sync(0xffffffffu, s, 2);
                if ((lane & 3) == 0) {
                    int row = m0 + (2 * wm + i) * 16 + r0 + h * 8;
                    atomicAdd(&sumexp[row], s);
                }
            }
        }
        return;
    }

    #pragma unroll
    for (int i = 0; i < 2; i++) {
        int mrow = m0 + (2 * wm + i) * 16 + r0;
        #pragma unroll
        for (int j = 0; j < 8; j++) {
            int col = n0 + (8 * wn + j) * 8 + c0v;
            if (mode == 0) {
                float* p0 = Cf + (size_t)mrow * ldc + col;
                float* p1 = p0 + (size_t)8 * ldc;
                *(float2*)p0 = make_float2(acc[i][j][0], acc[i][j][1]);
                *(float2*)p1 = make_float2(acc[i][j][2], acc[i][j][3]);
            } else if (mode == 1) {
                float* p0 = Cf + (size_t)mrow * ldc + col;
                float* p1 = p0 + (size_t)8 * ldc;
                float2 sc = *(const float2*)(scale + col);
                float2 v0 = *(const float2*)p0;
                float2 v1 = *(const float2*)p1;
                v0.x += sc.x * acc[i][j][0]; v0.y += sc.y * acc[i][j][1];
                v1.x += sc.x * acc[i][j][2]; v1.y += sc.y * acc[i][j][3];
                *(float2*)p0 = v0; *(float2*)p1 = v1;
            } else {
                bf16* p0 = Ch + (size_t)mrow * ldc + col;
                bf16* p1 = p0 + (size_t)8 * ldc;
                float a = fmaxf(acc[i][j][0], 0.f), b = fmaxf(acc[i][j][1], 0.f);
                float c = fmaxf(acc[i][j][2], 0.f), d = fmaxf(acc[i][j][3], 0.f);
                *(bf162*)p0 = __floats2bfloat162_rn(a * a, b * b);
                *(bf162*)p1 = __floats2bfloat162_rn(c * c, d * d);
            }
        }
    }
}

// ---------------- BF16 MMA causal flash attention (GQA) ----------------
// grid (32 qtiles, B*NH=32), block 128 (4 warps x 16 q-rows), 64-key tiles,
// cp.async double-buffered K/V, FA2 register-resident P.
#define FST 72   // halves per smem row (144B; conflict-free ldmatrix)
__global__ void __launch_bounds__(128) flash_mma_kernel(
    const bf16* __restrict__ Qh, const bf16* __restrict__ Kh,
    const bf16* __restrict__ Vh, bf16* __restrict__ O)
{
    __shared__ __align__(16) bf16 Qs[64 * FST];
    __shared__ __align__(16) bf16 Ks[2][64 * FST];
    __shared__ __align__(16) bf16 Vs[2][64 * FST];

    int qt = blockIdx.x, bh = blockIdx.y;
    int b = bh >> 4, head = bh & 15, kvh = head >> 2;
    int tid = threadIdx.x, lane = tid & 31, wid = tid >> 5;
    int t0 = b * SEQ + qt * 64;

    // stage Q (64 rows x 128B)
    #pragma unroll
    for (int i = 0; i < 4; i++) {
        int c = tid + i * 128;
        int r = c >> 3, off = (c & 7) * 8;
        *(uint4*)&Qs[r * FST + off] =
            *(const uint4*)(Qh + (size_t)(t0 + r) * (NH * HDIM) + head * HDIM + off);
    }
    __syncthreads();

    int tIdx = lane >> 3, rIn = lane & 7;
    uint32_t sQ = (uint32_t)__cvta_generic_to_shared(Qs);
    uint32_t sK = (uint32_t)__cvta_generic_to_shared(Ks);
    uint32_t sV = (uint32_t)__cvta_generic_to_shared(Vs);

    int qRow = wid * 16 + (tIdx & 1) * 8 + rIn;
    int qCol = (tIdx >> 1) * 8;
    uint4 aQ[4];
    #pragma unroll
    for (int c = 0; c < 4; c++)
        aQ[c] = ldsm4(sQ + (uint32_t)(qRow * FST + qCol + c * 16) * 2);

    float accO[8][4];
    #pragma unroll
    for (int j = 0; j < 8; j++)
        #pragma unroll
        for (int c = 0; c < 4; c++) accO[j][c] = 0.f;
    float m0 = -1e30f, m1 = -1e30f, l0 = 0.f, l1 = 0.f;

    int nkt = qt + 1;
    // prologue: tile 0 -> buffer 0
    {
        int k0 = b * SEQ;
        #pragma unroll
        for (int i = 0; i < 4; i++) {
            int c = tid + i * 128;
            int r = c >> 3, off = (c & 7) * 8;
            uint32_t d = (uint32_t)(r * FST + off) * 2;
            const bf16* kp = Kh + (size_t)(k0 + r) * (NKV * HDIM) + kvh * HDIM + off;
            const bf16* vp = Vh + (size_t)(k0 + r) * (NKV * HDIM) + kvh * HDIM + off;
            CP16(sK + d, kp);
            CP16(sV + d, vp);
        }
        CP_COMMIT();
    }
    int buf = 0;
    for (int kt = 0; kt < nkt; kt++) {
        if (kt + 1 < nkt) {
            int k0 = b * SEQ + (kt + 1) * 64;
            uint32_t bo = (uint32_t)((buf ^ 1) * 64 * FST) * 2;
            #pragma unroll
            for (int i = 0; i < 4; i++) {
                int c = tid + i * 128;
                int r = c >> 3, off = (c & 7) * 8;
                uint32_t d = bo + (uint32_t)(r * FST + off) * 2;
                const bf16* kp = Kh + (size_t)(k0 + r) * (NKV * HDIM) + kvh * HDIM + off;
                const bf16* vp = Vh + (size_t)(k0 + r) * (NKV * HDIM) + kvh * HDIM + off;
                CP16(sK + d, kp);
                CP16(sV + d, vp);
            }
        }
        CP_COMMIT();
        CP_WAIT1();
        __syncthreads();

        uint32_t bK = sK + (uint32_t)(buf * 64 * FST) * 2;
        uint32_t bV = sV + (uint32_t)(buf * 64 * FST) * 2;

        // S = Q @ K^T (64 keys)
        float accS[8][4];
        #pragma unroll
        for (int j = 0; j < 8; j++)
            #pragma unroll
            for (int c = 0; c < 4; c++) accS[j][c] = 0.f;
        #pragma unroll
        for (int g = 0; g < 4; g++) {
            #pragma unroll
            for (int c = 0; c < 4; c++) {
                uint4 bfr = ldsm4(bK + (uint32_t)((g * 16 + (tIdx & 1) * 8 + rIn) * FST
                                                  + (tIdx >> 1) * 8 + c * 16) * 2);
                mma_bf16(accS[2 * g],     aQ[c].x, aQ[c].y, aQ[c].z, aQ[c].w, bfr.x, bfr.z);
                mma_bf16(accS[2 * g + 1], aQ[c].x, aQ[c].y, aQ[c].z, aQ[c].w, bfr.y, bfr.w);
            }
        }

        // causal mask (diagonal tile only)
        int r0 = lane >> 2, cb = (lane & 3) * 2;
        if (kt == qt) {
            int qg0 = wid * 16 + r0;
            #pragma unroll
            for (int j = 0; j < 8; j++) {
                int kg = j * 8 + cb;
                if (kg > qg0)         accS[j][0] = -1e30f;
                if (kg + 1 > qg0)     accS[j][1] = -1e30f;
                if (kg > qg0 + 8)     accS[j][2] = -1e30f;
                if (kg + 1 > qg0 + 8) accS[j][3] = -1e30f;
            }
        }

        // online softmax (rows r0 / r0+8)
        float mx0 = -1e30f, mx1 = -1e30f;
        #pragma unroll
        for (int j = 0; j < 8; j++) {
            mx0 = fmaxf(mx0, fmaxf(accS[j][0], accS[j][1]));
            mx1 = fmaxf(mx1, fmaxf(accS[j][2], accS[j][3]));
        }
        mx0 = fmaxf(mx0, __shfl_xor_sync(0xffffffffu, mx0, 1));
        mx0 = fmaxf(mx0, __shfl_xor_sync(0xffffffffu, mx0, 2));
        mx1 = fmaxf(mx1, __shfl_xor_sync(0xffffffffu, mx1, 1));
        mx1 = fmaxf(mx1, __shfl_xor_sync(0xffffffffu, mx1, 2));
        float mn0 = fmaxf(m0, mx0), mn1 = fmaxf(m1, mx1);
        float al0 = __expf(m0 - mn0), al1 = __expf(m1 - mn1);
        m0 = mn0; m1 = mn1;
        float rs0 = 0.f, rs1 = 0.f;
        #pragma unroll
        for (int j = 0; j < 8; j++) {
            accS[j][0] = __expf(accS[j][0] - mn0);
            accS[j][1] = __expf(accS[j][1] - mn0);
            accS[j][2] = __expf(accS[j][2] - mn1);
            accS[j][3] = __expf(accS[j][3] - mn1);
            rs0 += accS[j][0] + accS[j][1];
            rs1 += accS[j][2] + accS[j][3];
        }
        rs0 += __shfl_xor_sync(0xffffffffu, rs0, 1);
        rs0 += __shfl_xor_sync(0xffffffffu, rs0, 2);
        rs1 += __shfl_xor_sync(0xffffffffu, rs1, 1);
        rs1 += __shfl_xor_sync(0xffffffffu, rs1, 2);
        l0 = l0 * al0 + rs0;
        l1 = l1 * al1 + rs1;
        #pragma unroll
        for (int j = 0; j < 8; j++) {
            accO[j][0] *= al0; accO[j][1] *= al0;
            accO[j][2] *= al1; accO[j][3] *= al1;
        }

        // P @ V  (P regs reused as A fragments)
        #pragma unroll
        for (int c = 0; c < 4; c++) {
            uint32_t a0 = packbf(accS[2 * c][0],     accS[2 * c][1]);
            uint32_t a1 = packbf(accS[2 * c][2],     accS[2 * c][3]);
            uint32_t a2 = packbf(accS[2 * c + 1][0], accS[2 * c + 1][1]);
            uint32_t a3 = packbf(accS[2 * c + 1][2], accS[2 * c + 1][3]);
            #pragma unroll
            for (int dg = 0; dg < 4; dg++) {
                uint4 bt = ldsm4t(bV + (uint32_t)((c * 16 + ((lane >> 3) & 1) * 8 + (lane & 7)) * FST
                                                  + dg * 16 + (lane >> 4) * 8) * 2);
                mma_bf16(accO[2 * dg],     a0, a1, a2, a3, bt.x, bt.y);
                mma_bf16(accO[2 * dg + 1], a0, a1, a2, a3, bt.z, bt.w);
            }
        }
        __syncthreads();
        buf ^= 1;
    }

    float li0 = 1.f / l0, li1 = 1.f / l1;
    int r0 = lane >> 2, cb = (lane & 3) * 2;
    int row0 = t0 + wid * 16 + r0;
    #pragma unroll
    for (int j = 0; j < 8; j++) {
        int col = head * HDIM + j * 8 + cb;
        *(bf162*)(O + (size_t)row0 * DMODEL + col) =
            __floats2bfloat162_rn(accO[j][0] * li0, accO[j][1] * li0);
        *(bf162*)(O + (size_t)(row0 + 8) * DMODEL + col) =
            __floats2bfloat162_rn(accO[j][2] * li1, accO[j][3] * li1);
    }
}

// ---------------- misc small kernels ----------------
__global__ void copy_kernel(float4* __restrict__ dst, const float4* __restrict__ src, int n4) {
    int i = blockIdx.x * blockDim.x + threadIdx.x;
    if (i < n4) dst[i] = src[i];
}
__global__ void zero_kernel(float* __restrict__ p, int n) {
    int i = blockIdx.x * blockDim.x + threadIdx.x;
    if (i < n) p[i] = 0.f;
}
__global__ void tgt_kernel(const bf16* __restrict__ XR, const float* __restrict__ u_emb,
                           const int* __restrict__ y, float* __restrict__ tgt) {
    int row = blockIdx.x * 4 + (threadIdx.x >> 5);
    int lane = threadIdx.x & 31;
    if (row >= TT) return;
    int t = y[row];
    const bf16* h = XR + (size_t)row * DMODEL;
    const float* u = u_emb + (size_t)t * 512;
    float s = 0.f;
    for (int i = lane * 4; i < 512; i += 128) {
        bf162 h0 = *(const bf162*)(h + i);
        bf162 h1 = *(const bf162*)(h + i + 2);
        float4 uv = *(const float4*)(u + i);
        s += __bfloat162float(h0.x) * uv.x + __bfloat162float(h0.y) * uv.y
           + __bfloat162float(h1.x) * uv.z + __bfloat162float(h1.y) * uv.w;
    }
    #pragma unroll
    for (int off = 16; off; off >>= 1) s += __shfl_xor_sync(0xffffffffu, s, off);
    if (lane == 0) tgt[row] = 30.f * tanhf(s * (1.f / 30.f));
}
__global__ void loss_kernel(const float* __restrict__ sumexp, const float* __restrict__ tgt,
                            float* __restrict__ out) {
    float s = 0.f;
    for (int i = threadIdx.x; i < TT; i += 256)
        s += logf(sumexp[i]) - tgt[i];
    float tot = block_sum_256(s);
    if (threadIdx.x == 0) out[0] = tot * (1.f / TT);
}

// ---------------- host orchestration ----------------
static inline void gemm_launch(const bf16* A, int lda, const bf16* W,
                               float* Cf, bf16* Ch, int ldc,
                               const float* scale, float* sumexp,
                               int M, int N, int K, int mode) {
    dim3 grid((N + 127) / 128, M / 128);
    gemm_bf16_kernel<<<grid, 256>>>(A, lda, W, Cf, Ch, ldc, scale, sumexp, M, N, K, mode);
}

extern "C" void kernel_launch(void* const* d_in, const int* in_sizes, int n_in,
                              void* d_out, int out_size) {
    const int*   ids     = (const int*)d_in[0];
    const int*   y       = (const int*)d_in[1];
    const float* u_emb   = (const float*)d_in[2];
    const float* b_emb   = (const float*)d_in[3];
    const float* Wq      = (const float*)d_in[4];
    const float* Wk      = (const float*)d_in[5];
    const float* Wv      = (const float*)d_in[6];
    const float* Wo      = (const float*)d_in[7];
    const float* qg      = (const float*)d_in[8];
    const float* a_scale = (const float*)d_in[9];
    const float* m_scale = (const float*)d_in[10];
    const float* rm      = (const float*)d_in[11];
    const float* Wf      = (const float*)d_in[12];
    const float* Wo2     = (const float*)d_in[13];
    const float* sw      = (const float*)d_in[14];

    float *X, *X0, *QKV, *SK, *COS, *SIN, *SUM, *TGT;
    bf16 *XRh, *MHh, *ATTh, *Qh, *Kh, *Vh, *WQKVh, *WOh, *WFh, *WO2h, *UEh;
    cudaGetSymbolAddress((void**)&X,     g_X);
    cudaGetSymbolAddress((void**)&X0,    g_X0);
    cudaGetSymbolAddress((void**)&QKV,   g_QKV);
    cudaGetSymbolAddress((void**)&SK,    g_SK);
    cudaGetSymbolAddress((void**)&COS,   g_COS);
    cudaGetSymbolAddress((void**)&SIN,   g_SIN);
    cudaGetSymbolAddress((void**)&SUM,   g_SUMEXP);
    cudaGetSymbolAddress((void**)&TGT,   g_TGT);
    cudaGetSymbolAddress((void**)&XRh,   g_XRh);
    cudaGetSymbolAddress((void**)&MHh,   g_MHh);
    cudaGetSymbolAddress((void**)&ATTh,  g_ATTh);
    cudaGetSymbolAddress((void**)&Qh,    g_Qh);
    cudaGetSymbolAddress((void**)&Kh,    g_Kh);
    cudaGetSymbolAddress((void**)&Vh,    g_Vh);
    cudaGetSymbolAddress((void**)&WQKVh, g_WQKVh);
    cudaGetSymbolAddress((void**)&WOh,   g_WOh);
    cudaGetSymbolAddress((void**)&WFh,   g_WFh);
    cudaGetSymbolAddress((void**)&WO2h,  g_WO2h);
    cudaGetSymbolAddress((void**)&UEh,   g_UEh);

    rope_table_kernel<<<(SEQ * 32 + 255) / 256, 256>>>(COS, SIN);
    {
        int tot = LNUM * QKVD * (DMODEL / 4);
        pack_qkv_kernel<<<(tot + 255) / 256, 256>>>(Wq, Wk, Wv, (bf162*)WQKVh);
        int n4;
        n4 = LNUM * DMODEL * DMODEL / 4;
        f2h_kernel<<<(n4 + 255) / 256, 256>>>((const float4*)Wo, (bf162*)WOh, n4);
        n4 = LNUM * MLPD * DMODEL / 4;
        f2h_kernel<<<(n4 + 255) / 256, 256>>>((const float4*)Wf, (bf162*)WFh, n4);
        f2h_kernel<<<(n4 + 255) / 256, 256>>>((const float4*)Wo2, (bf162*)WO2h, n4);
        n4 = VSZ * 512 / 4;
        f2h_kernel<<<(n4 + 255) / 256, 256>>>((const float4*)u_emb, (bf162*)UEh, n4);
    }
    embed_kernel<<<TT, 256>>>(ids, u_emb, b_emb, X, X0);

    auto run_block = [&](int l, const float* skip, const float* swv) {
        mix_rmsn_kernel<<<TT, 256>>>(X, X0, XRh, rm + (size_t)l * 2 * DMODEL, skip, swv);
        gemm_launch(XRh, DMODEL, WQKVh + (size_t)l * QKVD * DMODEL, QKV, nullptr, QKVD,
                    nullptr, nullptr, TT, QKVD, DMODEL, 0);
        qkrope_kernel<<<TT * (NH + 2 * NKV) / 8, 256>>>(QKV, Qh, Kh, Vh, COS, SIN,
                                                        qg + (size_t)l * NH);
        flash_mma_kernel<<<dim3(32, 32), 128>>>(Qh, Kh, Vh, ATTh);
        gemm_launch(ATTh, DMODEL, WOh + (size_t)l * DMODEL * DMODEL, X, nullptr, DMODEL,
                    a_scale + (size_t)l * DMODEL, nullptr, TT, DMODEL, DMODEL, 1);
        rmsn_kernel<<<TT, 256>>>(X, XRh);
        gemm_launch(XRh, DMODEL, WFh + (size_t)l * MLPD * DMODEL, nullptr, MHh, MLPD,
                    nullptr, nullptr, TT, MLPD, DMODEL, 2);
        gemm_launch(MHh, MLPD, WO2h + (size_t)l * DMODEL * MLPD, X, nullptr, DMODEL,
                    m_scale + (size_t)l * DMODEL, nullptr, TT, DMODEL, MLPD, 1);
    };

    // forward pass + skip stash
    for (int i = 0; i < LNUM; i++) {
        run_block(i, nullptr, nullptr);
        copy_kernel<<<(TT * DMODEL / 4 + 255) / 256, 256>>>(
            (float4*)(SK + (size_t)i * TT * DMODEL), (const float4*)X, TT * DMODEL / 4);
    }
    // reverse pass with skips
    for (int i = 0; i < LNUM; i++) {
        int j = LNUM - 1 - i;
        run_block(j, SK + (size_t)j * TT * DMODEL, sw + (size_t)i * DMODEL);
    }

    // final norm + loss
    rmsn_kernel<<<TT, 256>>>(X, XRh);
    zero_kernel<<<(TT + 255) / 256, 256>>>(SUM, TT);
    gemm_launch(XRh, DMODEL, UEh, nullptr, nullptr, VSZ, nullptr, SUM, TT, VSZ, 512, 3);
    tgt_kernel<<<TT / 4, 128>>>(XRh, u_emb, y, TGT);
    loss_kernel<<<1, 256>>>(SUM, TGT, (float*)d_out);
}

// round 11
// speedup vs baseline: 6.3431x; 1.0024x over previous
#include <cuda_runtime.h>
#include <cuda_bf16.h>
#include <math.h>
#include <stdint.h>

// ---------------- model constants ----------------
#define LNUM 6
#define DMODEL 1024
#define NH 16
#define NKV 4
#define HDIM 64
#define BATCH 2
#define SEQ 2048
#define TT (BATCH*SEQ)          // 4096 tokens
#define VSZ 50257
#define HSZ 4096
#define MLPD 3072
#define QKVD 1536               // 1024 + 256 + 256
#define EPSF 1.1920929e-07f

typedef __nv_bfloat16 bf16;
typedef __nv_bfloat162 bf162;

// ---------------- scratch (device globals; no allocation allowed) ----------------
__device__ float g_X[TT*DMODEL];
__device__ float g_X0[TT*DMODEL];
__device__ float g_QKV[TT*QKVD];
__device__ float g_SK[LNUM*TT*DMODEL];
__device__ float g_COS[SEQ*32];
__device__ float g_SIN[SEQ*32];
__device__ float g_SUMEXP[TT];
__device__ float g_TGT[TT];
__device__ bf16  g_XRh[TT*DMODEL];
__device__ bf16  g_MHh[TT*MLPD];
__device__ bf16  g_ATTh[TT*DMODEL];
__device__ bf16  g_Qh[TT*NH*HDIM];
__device__ bf16  g_Kh[TT*NKV*HDIM];
__device__ bf16  g_Vh[TT*NKV*HDIM];
__device__ bf16  g_WQKVh[(size_t)LNUM*QKVD*DMODEL];
__device__ bf16  g_WOh[(size_t)LNUM*DMODEL*DMODEL];
__device__ bf16  g_WFh[(size_t)LNUM*MLPD*DMODEL];
__device__ bf16  g_WO2h[(size_t)LNUM*DMODEL*MLPD];
__device__ bf16  g_UEh[(size_t)VSZ*512];

// ---------------- helpers ----------------
__device__ __forceinline__ float block_sum_256(float v) {
    __shared__ float sh[8];
    #pragma unroll
    for (int o = 16; o; o >>= 1) v += __shfl_xor_sync(0xffffffffu, v, o);
    if ((threadIdx.x & 31) == 0) sh[threadIdx.x >> 5] = v;
    __syncthreads();
    if (threadIdx.x == 0) {
        float s = 0.f;
        #pragma unroll
        for (int i = 0; i < 8; i++) s += sh[i];
        sh[0] = s;
    }
    __syncthreads();
    return sh[0];
}

__device__ __forceinline__ void mma_bf16(float* c, uint32_t a0, uint32_t a1,
                                         uint32_t a2, uint32_t a3,
                                         uint32_t b0, uint32_t b1) {
    asm volatile(
        "mma.sync.aligned.m16n8k16.row.col.f32.bf16.bf16.f32 "
        "{%0,%1,%2,%3}, {%4,%5,%6,%7}, {%8,%9}, {%0,%1,%2,%3};"
        : "+f"(c[0]), "+f"(c[1]), "+f"(c[2]), "+f"(c[3])
        : "r"(a0), "r"(a1), "r"(a2), "r"(a3), "r"(b0), "r"(b1));
}

__device__ __forceinline__ uint4 ldsm4(uint32_t addr) {
    uint4 r;
    asm volatile("ldmatrix.sync.aligned.m8n8.x4.shared.b16 {%0,%1,%2,%3}, [%4];"
        : "=r"(r.x), "=r"(r.y), "=r"(r.z), "=r"(r.w) : "r"(addr));
    return r;
}
__device__ __forceinline__ uint4 ldsm4t(uint32_t addr) {
    uint4 r;
    asm volatile("ldmatrix.sync.aligned.m8n8.x4.trans.shared.b16 {%0,%1,%2,%3}, [%4];"
        : "=r"(r.x), "=r"(r.y), "=r"(r.z), "=r"(r.w) : "r"(addr));
    return r;
}
__device__ __forceinline__ uint32_t packbf(float x, float y) {
    bf162 r = __floats2bfloat162_rn(x, y);
    return *(uint32_t*)&r;
}

#define CP16(dst, src) asm volatile("cp.async.cg.shared.global [%0], [%1], 16;" :: "r"(dst), "l"(src))
#define CP_COMMIT()    asm volatile("cp.async.commit_group;")
#define CP_WAIT1()     asm volatile("cp.async.wait_group 1;")

// ---------------- rope tables ----------------
__global__ void rope_table_kernel(float* __restrict__ cosT, float* __restrict__ sinT) {
    int idx = blockIdx.x * 256 + threadIdx.x;
    if (idx >= SEQ * 32) return;
    int t = idx >> 5, j = idx & 31;
    double f = pow(10000.0, -(double)j / 32.0);
    double a = (double)t * f;
    cosT[idx] = (float)cos(a);
    sinT[idx] = (float)sin(a);
}

// ---------------- all fp32 -> bf16 weight converts in one launch ----------------
__global__ void f2h_all_kernel(const float4* __restrict__ s1, bf162* __restrict__ d1, int n1,
                               const float4* __restrict__ s2, bf162* __restrict__ d2, int n2,
                               const float4* __restrict__ s3, bf162* __restrict__ d3, int n3,
                               const float4* __restrict__ s4, bf162* __restrict__ d4, int n4) {
    long i = (long)blockIdx.x * 256 + threadIdx.x;
    const float4* s; bf162* d;
    if (i < n1) { s = s1; d = d1; }
    else if ((i -= n1) < n2) { s = s2; d = d2; }
    else if ((i -= n2) < n3) { s = s3; d = d3; }
    else if ((i -= n3) < n4) { s = s4; d = d4; }
    else return;
    float4 v = s[i];
    d[2 * i]     = __floats2bfloat162_rn(v.x, v.y);
    d[2 * i + 1] = __floats2bfloat162_rn(v.z, v.w);
}

// ---------------- pack Wq/Wk/Wv -> bf16 WQKV[l][1536][1024] ----------------
__global__ void pack_qkv_kernel(const float* __restrict__ Wq, const float* __restrict__ Wk,
                                const float* __restrict__ Wv, bf162* __restrict__ out) {
    const int ROWF4 = DMODEL / 4;
    const int TOT = LNUM * QKVD * ROWF4;
    int i = blockIdx.x * 256 + threadIdx.x;
    if (i >= TOT) return;
    int rowg = i / ROWF4, c = i % ROWF4;
    int l = rowg / QKVD, r = rowg % QKVD;
    const float4* src;
    if (r < 1024)      src = (const float4*)(Wq + ((size_t)l * 1024 + r) * DMODEL);
    else if (r < 1280) src = (const float4*)(Wk + ((size_t)l * 256 + (r - 1024)) * DMODEL);
    else               src = (const float4*)(Wv + ((size_t)l * 256 + (r - 1280)) * DMODEL);
    float4 v = src[c];
    out[2 * i]     = __floats2bfloat162_rn(v.x, v.y);
    out[2 * i + 1] = __floats2bfloat162_rn(v.z, v.w);
}

// ---------------- embedding + rmsnorm ----------------
__global__ void embed_kernel(const int* __restrict__ ids, const float* __restrict__ u_emb,
                             const float* __restrict__ b_emb,
                             float* __restrict__ X, float* __restrict__ X0) {
    int t = blockIdx.x;
    int s = t & (SEQ - 1);
    int id = ids[t];
    int pi = (s == 0) ? 0 : ids[t - 1];
    int bi = ((pi % HSZ) * (VSZ % HSZ) % HSZ + id % HSZ) % HSZ;
    int tid = threadIdx.x;
    float v[4];
    float ssq = 0.f;
    #pragma unroll
    for (int i = 0; i < 4; i++) {
        int d = i * 256 + tid;
        float x = (d < 512) ? u_emb[(size_t)id * 512 + d] : b_emb[(size_t)bi * 512 + (d - 512)];
        v[i] = x; ssq += x * x;
    }
    float tot = block_sum_256(ssq);
    float r = rsqrtf(tot * (1.f / DMODEL) + EPSF);
    #pragma unroll
    for (int i = 0; i < 4; i++) {
        int d = i * 256 + tid;
        float o = v[i] * r;
        X[(size_t)t * DMODEL + d] = o;
        X0[(size_t)t * DMODEL + d] = o;
    }
}

// ---------------- residual mix (+optional skip) then rmsnorm -> bf16 ----------------
__global__ void mix_rmsn_kernel(float* __restrict__ X, const float* __restrict__ X0,
                                bf16* __restrict__ XR, const float* __restrict__ rm,
                                const float* __restrict__ skip, const float* __restrict__ sw) {
    int t = blockIdx.x, tid = threadIdx.x;
    float v[4]; float ssq = 0.f;
    #pragma unroll
    for (int i = 0; i < 4; i++) {
        int d = i * 256 + tid;
        size_t off = (size_t)t * DMODEL + d;
        float x = X[off];
        if (skip) x += sw[d] * skip[off];
        x = rm[d] * x + rm[DMODEL + d] * X0[off];
        v[i] = x; ssq += x * x;
    }
    float tot = block_sum_256(ssq);
    float r = rsqrtf(tot * (1.f / DMODEL) + EPSF);
    #pragma unroll
    for (int i = 0; i < 4; i++) {
        int d = i * 256 + tid;
        size_t off = (size_t)t * DMODEL + d;
        X[off] = v[i];
        XR[off] = __float2bfloat16(v[i] * r);
    }
}

// ---------------- plain rmsnorm -> bf16 ----------------
__global__ void rmsn_kernel(const float* __restrict__ X, bf16* __restrict__ XR) {
    int t = blockIdx.x, tid = threadIdx.x;
    float v[4]; float ssq = 0.f;
    #pragma unroll
    for (int i = 0; i < 4; i++) {
        int d = i * 256 + tid;
        v[i] = X[(size_t)t * DMODEL + d];
        ssq += v[i] * v[i];
    }
    float tot = block_sum_256(ssq);
    float r = rsqrtf(tot * (1.f / DMODEL) + EPSF);
    #pragma unroll
    for (int i = 0; i < 4; i++) {
        int d = i * 256 + tid;
        XR[(size_t)t * DMODEL + d] = __float2bfloat16(v[i] * r);
    }
}

// ---------------- per-head rmsnorm + rope, fp32 QKV -> bf16 Qh/Kh/Vh ----------------
__device__ __forceinline__ void rope_norm_store(const float* __restrict__ src,
                                                bf16* __restrict__ dst, int t, int lane,
                                                float gain,
                                                const float* __restrict__ cosT,
                                                const float* __restrict__ sinT) {
    int s = t & (SEQ - 1);
    float v1 = src[lane], v2 = src[lane + 32];
    float ssq = v1 * v1 + v2 * v2;
    #pragma unroll
    for (int off = 16; off; off >>= 1) ssq += __shfl_xor_sync(0xffffffffu, ssq, off);
    float r = rsqrtf(ssq * (1.f / HDIM) + EPSF);
    v1 *= r; v2 *= r;
    float c = cosT[s * 32 + lane], sn = sinT[s * 32 + lane];
    dst[lane]      = __float2bfloat16((v1 * c + v2 * sn) * gain);
    dst[lane + 32] = __float2bfloat16((-v1 * sn + v2 * c) * gain);
}

__global__ void qkrope_kernel(const float* __restrict__ QKV,
                              bf16* __restrict__ Qh, bf16* __restrict__ Kh, bf16* __restrict__ Vh,
                              const float* __restrict__ cosT, const float* __restrict__ sinT,
                              const float* __restrict__ qg) {
    int gw = blockIdx.x * 8 + (threadIdx.x >> 5);
    int lane = threadIdx.x & 31;
    const int NQ = TT * NH, NK = TT * NKV;
    if (gw < NQ) {
        int t = gw >> 4, h = gw & 15;
        rope_norm_store(QKV + (size_t)t * QKVD + h * HDIM,
                        Qh + (size_t)t * (NH * HDIM) + h * HDIM,
                        t, lane, qg[h] * 0.125f, cosT, sinT);  // fold 1/sqrt(64)
    } else if (gw < NQ + NK) {
        int g2 = gw - NQ;
        int t = g2 >> 2, h = g2 & 3;
        rope_norm_store(QKV + (size_t)t * QKVD + 1024 + h * HDIM,
                        Kh + (size_t)t * (NKV * HDIM) + h * HDIM,
                        t, lane, 1.f, cosT, sinT);
    } else {
        int g3 = gw - NQ - NK;
        if (g3 >= TT * NKV) return;
        int t = g3 >> 2, h = g3 & 3;
        const float* src = QKV + (size_t)t * QKVD + 1280 + h * HDIM;
        bf16* dst = Vh + (size_t)t * (NKV * HDIM) + h * HDIM;
        dst[lane]      = __float2bfloat16(src[lane]);
        dst[lane + 32] = __float2bfloat16(src[lane + 32]);
    }
}

// ---------------- BF16 tensor-core GEMM: C[M,N] = A[M,K(lda)] @ W[N,K]^T ----------------
// Block 128x128, BK=32, 8 warps (warp tile 32x64), mma.m16n8k16.bf16,
// cp.async 3-stage pipeline (one barrier per k-tile), ldmatrix fragment loads.
// mode 0: Cf = acc (fp32)      mode 1: Cf += scale[n]*acc (in-place; also -> Csk if set)
// mode 2: Ch = relu(acc)^2 (bf16)
// mode 3: atomicAdd(sumexp[m], sum_n exp(30*tanh(acc/30)))
#define AS_STRIDE 40            // halves per smem row (80B; conflict-free ldmatrix)
#define ABUF (128*AS_STRIDE)    // halves per buffer
#define GEMM_SMEM (6*ABUF*2)    // 3 stages x (A+B) in bytes = 61440
__global__ void __launch_bounds__(256) gemm_bf16_kernel(
    const bf16* __restrict__ A, int lda, const bf16* __restrict__ W,
    float* __restrict__ Cf, bf16* __restrict__ Ch, float* __restrict__ Csk, int ldc,
    const float* __restrict__ scale, float* __restrict__ sumexp,
    int M, int N, int K, int mode)
{
    extern __shared__ __align__(16) bf16 dynsm[];
    bf16* Asm = dynsm;             // 3*ABUF halves
    bf16* Bsm = dynsm + 3 * ABUF;  // 3*ABUF halves

    int tid = threadIdx.x;
    int lane = tid & 31, wid = tid >> 5;
    int wm = wid & 3, wn = wid >> 2;       // warp tile: rows wm*32, cols wn*64
    int m0 = blockIdx.y * 128, n0 = blockIdx.x * 128;

    // cp.async assignment: thread -> row tid>>1, halves (tid&1)*16 .. +15 (two 16B chunks)
    int arow = tid >> 1;
    int ac8 = (tid & 1) * 16;
    const bf16* ApA = A + (size_t)(m0 + arow) * lda + ac8;
    int wrow = n0 + arow;
    int wsafe = (wrow < N) ? wrow : (N - 1);
    const bf16* ApW = W + (size_t)wsafe * K + ac8;
    uint32_t sA = (uint32_t)__cvta_generic_to_shared(Asm);
    uint32_t sB = (uint32_t)__cvta_generic_to_shared(Bsm);
    uint32_t dA = sA + (uint32_t)(arow * AS_STRIDE + ac8) * 2;
    uint32_t dB = sB + (uint32_t)(arow * AS_STRIDE + ac8) * 2;

    // ldmatrix per-lane offsets
    int tIdx = lane >> 3, rIn = lane & 7;
    int aRow = wm * 32 + (tIdx & 1) * 8 + rIn;
    int kCol = (tIdx >> 1) * 8;
    uint32_t aOff[2][2], bOff[4][2];
    #pragma unroll
    for (int i = 0; i < 2; i++)
        #pragma unroll
        for (int s = 0; s < 2; s++)
            aOff[i][s] = (uint32_t)(((aRow + i * 16) * AS_STRIDE) + kCol + s * 16) * 2;
    #pragma unroll
    for (int jj = 0; jj < 4; jj++)
        #pragma unroll
        for (int s = 0; s < 2; s++)
            bOff[jj][s] = (uint32_t)(((wn * 64 + jj * 16 + (tIdx & 1) * 8 + rIn) * AS_STRIDE) + kCol + s * 16) * 2;

    float acc[2][8][4];
    #pragma unroll
    for (int i = 0; i < 2; i++)
        #pragma unroll
        for (int j = 0; j < 8; j++)
            #pragma unroll
            for (int c = 0; c < 4; c++) acc[i][j][c] = 0.f;

    int nk = K >> 5;
    // prologue: tiles 0,1 -> buffers 0,1 (separate commit groups)
    {
        CP16(dA, ApA); CP16(dA + 16, ApA + 8);
        CP16(dB, ApW); CP16(dB + 16, ApW + 8);
        CP_COMMIT();
        if (nk > 1) {
            uint32_t bo = ABUF * 2;
            CP16(dA + bo, ApA + 32); CP16(dA + bo + 16, ApA + 40);
            CP16(dB + bo, ApW + 32); CP16(dB + bo + 16, ApW + 40);
        }
        CP_COMMIT();
    }
    int b0 = 0, b1 = 1, b2 = 2;
    for (int kt = 0; kt < nk; kt++) {
        CP_WAIT1();          // tile kt's loads complete (<=1 group pending)
        __syncthreads();     // visible to all warps; prior tile's readers done
        if (kt + 2 < nk) {   // issue tile kt+2 into the buffer freed at kt-1
            int k0 = (kt + 2) << 5;
            uint32_t bo = (uint32_t)b2 * (ABUF * 2);
            CP16(dA + bo, ApA + k0); CP16(dA + bo + 16, ApA + k0 + 8);
            CP16(dB + bo, ApW + k0); CP16(dB + bo + 16, ApW + k0 + 8);
        }
        CP_COMMIT();

        uint32_t bA = sA + (uint32_t)b0 * (ABUF * 2);
        uint32_t bB = sB + (uint32_t)b0 * (ABUF * 2);
        #pragma unroll
        for (int s = 0; s < 2; s++) {
            uint4 af0 = ldsm4(bA + aOff[0][s]);
            uint4 af1 = ldsm4(bA + aOff[1][s]);
            #pragma unroll
            for (int jj = 0; jj < 4; jj++) {
                uint4 bfr = ldsm4(bB + bOff[jj][s]);
                mma_bf16(acc[0][2 * jj],     af0.x, af0.y, af0.z, af0.w, bfr.x, bfr.z);
                mma_bf16(acc[0][2 * jj + 1], af0.x, af0.y, af0.z, af0.w, bfr.y, bfr.w);
                mma_bf16(acc[1][2 * jj],     af1.x, af1.y, af1.z, af1.w, bfr.x, bfr.z);
                mma_bf16(acc[1][2 * jj + 1], af1.x, af1.y, af1.z, af1.w, bfr.y, bfr.w);
            }
        }
        int t = b0; b0 = b1; b1 = b2; b2 = t;
    }

    int r0 = lane >> 2, c0v = (lane & 3) * 2;

    if (mode == 3) {
        #pragma unroll
        for (int i = 0; i < 2; i++) {
            #pragma unroll
            for (int h = 0; h < 2; h++) {
                float s = 0.f;
                #pragma unroll
                for (int j = 0; j < 8; j++) {
                    int col = n0 + (8 * wn + j) * 8 + c0v;
                    if (col < N)     s += __expf(30.f * tanhf(acc[i][j][h * 2 + 0] * (1.f / 30.f)));
                    if (col + 1 < N) s += __expf(30.f * tanhf(acc[i][j][h * 2 + 1] * (1.f / 30.f)));
                }
                s += __shfl_xor_sync(0xffffffffu, s, 1);
                s += __shfl_xor_sync(0xffffffffu, s, 2);
                if ((lane & 3) == 0) {
                    int row = m0 + (2 * wm + i) * 16 + r0 + h * 8;
                    atomicAdd(&sumexp[row], s);
                }
            }
        }
        return;
    }

    #pragma unroll
    for (int i = 0; i < 2; i++) {
        int mrow = m0 + (2 * wm + i) * 16 + r0;
        #pragma unroll
        for (int j = 0; j < 8; j++) {
            int col = n0 + (8 * wn + j) * 8 + c0v;
            if (mode == 0) {
                float* p0 = Cf + (size_t)mrow * ldc + col;
                float* p1 = p0 + (size_t)8 * ldc;
                *(float2*)p0 = make_float2(acc[i][j][0], acc[i][j][1]);
                *(float2*)p1 = make_float2(acc[i][j][2], acc[i][j][3]);
            } else if (mode == 1) {
                float* p0 = Cf + (size_t)mrow * ldc + col;
                float* p1 = p0 + (size_t)8 * ldc;
                float2 sc = *(const float2*)(scale + col);
                float2 v0 = *(const float2*)p0;
                float2 v1 = *(const float2*)p1;
                v0.x += sc.x * acc[i][j][0]; v0.y += sc.y * acc[i][j][1];
                v1.x += sc.x * acc[i][j][2]; v1.y += sc.y * acc[i][j][3];
                *(float2*)p0 = v0; *(float2*)p1 = v1;
                if (Csk) {
                    float* q0 = Csk + (size_t)mrow * ldc + col;
                    float* q1 = q0 + (size_t)8 * ldc;
                    *(float2*)q0 = v0; *(float2*)q1 = v1;
                }
            } else { // mode 2: relu^2 -> bf16
                bf16* p0 = Ch + (size_t)mrow * ldc + col;
                bf16* p1 = p0 + (size_t)8 * ldc;
                float a = fmaxf(acc[i][j][0], 0.f), b = fmaxf(acc[i][j][1], 0.f);
                float c = fmaxf(acc[i][j][2], 0.f), d = fmaxf(acc[i][j][3], 0.f);
                *(bf162*)p0 = __floats2bfloat162_rn(a * a, b * b);
                *(bf162*)p1 = __floats2bfloat162_rn(c * c, d * d);
            }
        }
    }
}

// ---------------- BF16 MMA causal flash attention (GQA) ----------------
#define FST 72   // halves per smem row (144B; conflict-free ldmatrix)
__global__ void __launch_bounds__(128) flash_mma_kernel(
    const bf16* __restrict__ Qh, const bf16* __restrict__ Kh,
    const bf16* __restrict__ Vh, bf16* __restrict__ O)
{
    __shared__ __align__(16) bf16 Qs[64 * FST];
    __shared__ __align__(16) bf16 Ks[2][64 * FST];
    __shared__ __align__(16) bf16 Vs[2][64 * FST];

    int qt = blockIdx.x, bh = blockIdx.y;
    int b = bh >> 4, head = bh & 15, kvh = head >> 2;
    int tid = threadIdx.x, lane = tid & 31, wid = tid >> 5;
    int t0 = b * SEQ + qt * 64;

    #pragma unroll
    for (int i = 0; i < 4; i++) {
        int c = tid + i * 128;
        int r = c >> 3, off = (c & 7) * 8;
        *(uint4*)&Qs[r * FST + off] =
            *(const uint4*)(Qh + (size_t)(t0 + r) * (NH * HDIM) + head * HDIM + off);
    }
    __syncthreads();

    int tIdx = lane >> 3, rIn = lane & 7;
    uint32_t sQ = (uint32_t)__cvta_generic_to_shared(Qs);
    uint32_t sK = (uint32_t)__cvta_generic_to_shared(Ks);
    uint32_t sV = (uint32_t)__cvta_generic_to_shared(Vs);

    int qRow = wid * 16 + (tIdx & 1) * 8 + rIn;
    int qCol = (tIdx >> 1) * 8;
    uint4 aQ[4];
    #pragma unroll
    for (int c = 0; c < 4; c++)
        aQ[c] = ldsm4(sQ + (uint32_t)(qRow * FST + qCol + c * 16) * 2);

    float accO[8][4];
    #pragma unroll
    for (int j = 0; j < 8; j++)
        #pragma unroll
        for (int c = 0; c < 4; c++) accO[j][c] = 0.f;
    float m0 = -1e30f, m1 = -1e30f, l0 = 0.f, l1 = 0.f;

    int nkt = qt + 1;
    {
        int k0 = b * SEQ;
        #pragma unroll
        for (int i = 0; i < 4; i++) {
            int c = tid + i * 128;
            int r = c >> 3, off = (c & 7) * 8;
            uint32_t dd = (uint32_t)(r * FST + off) * 2;
            CP16(sK + dd, Kh + (size_t)(k0 + r) * (NKV * HDIM) + kvh * HDIM + off);
            CP16(sV + dd, Vh + (size_t)(k0 + r) * (NKV * HDIM) + kvh * HDIM + off);
        }
        CP_COMMIT();
    }
    int buf = 0;
    for (int kt = 0; kt < nkt; kt++) {
        if (kt + 1 < nkt) {
            int k0 = b * SEQ + (kt + 1) * 64;
            uint32_t bo = (uint32_t)((buf ^ 1) * 64 * FST) * 2;
            #pragma unroll
            for (int i = 0; i < 4; i++) {
                int c = tid + i * 128;
                int r = c >> 3, off = (c & 7) * 8;
                uint32_t dd = bo + (uint32_t)(r * FST + off) * 2;
                CP16(sK + dd, Kh + (size_t)(k0 + r) * (NKV * HDIM) + kvh * HDIM + off);
                CP16(sV + dd, Vh + (size_t)(k0 + r) * (NKV * HDIM) + kvh * HDIM + off);
            }
        }
        CP_COMMIT();
        CP_WAIT1();
        __syncthreads();

        uint32_t bK = sK + (uint32_t)(buf * 64 * FST) * 2;
        uint32_t bV = sV + (uint32_t)(buf * 64 * FST) * 2;

        float accS[8][4];
        #pragma unroll
        for (int j = 0; j < 8; j++)
            #pragma unroll
            for (int c = 0; c < 4; c++) accS[j][c] = 0.f;
        #pragma unroll
        for (int g = 0; g < 4; g++) {
            #pragma unroll
            for (int c = 0; c < 4; c++) {
                uint4 bfr = ldsm4(bK + (uint32_t)((g * 16 + (tIdx & 1) * 8 + rIn) * FST
                                                  + (tIdx >> 1) * 8 + c * 16) * 2);
                mma_bf16(accS[2 * g],     aQ[c].x, aQ[c].y, aQ[c].z, aQ[c].w, bfr.x, bfr.z);
                mma_bf16(accS[2 * g + 1], aQ[c].x, aQ[c].y, aQ[c].z, aQ[c].w, bfr.y, bfr.w);
            }
        }

        int r0 = lane >> 2, cbm = (lane & 3) * 2;
        if (kt == qt) {
            int qg0 = wid * 16 + r0;
            #pragma unroll
            for (int j = 0; j < 8; j++) {
                int kg = j * 8 + cbm;
                if (kg > qg0)         accS[j][0] = -1e30f;
                if (kg + 1 > qg0)     accS[j][1] = -1e30f;
                if (kg > qg0 + 8)     accS[j][2] = -1e30f;
                if (kg + 1 > qg0 + 8) accS[j][3] = -1e30f;
            }
        }

        float mx0 = -1e30f, mx1 = -1e30f;
        #pragma unroll
        for (int j = 0; j < 8; j++) {
            mx0 = fmaxf(mx0, fmaxf(accS[j][0], accS[j][1]));
            mx1 = fmaxf(mx1, fmaxf(accS[j][2], accS[j][3]));
        }
        mx0 = fmaxf(mx0, __shfl_xor_sync(0xffffffffu, mx0, 1));
        mx0 = fmaxf(mx0, __shfl_xor_sync(0xffffffffu, mx0, 2));
        mx1 = fmaxf(mx1, __shfl_xor_sync(0xffffffffu, mx1, 1));
        mx1 = fmaxf(mx1, __shfl_xor_sync(0xffffffffu, mx1, 2));
        float mn0 = fmaxf(m0, mx0), mn1 = fmaxf(m1, mx1);
        float al0 = __expf(m0 - mn0), al1 = __expf(m1 - mn1);
        m0 = mn0; m1 = mn1;
        float rs0 = 0.f, rs1 = 0.f;
        #pragma unroll
        for (int j = 0; j < 8; j++) {
            accS[j][0] = __expf(accS[j][0] - mn0);
            accS[j][1] = __expf(accS[j][1] - mn0);
            accS[j][2] = __expf(accS[j][2] - mn1);
            accS[j][3] = __expf(accS[j][3] - mn1);
            rs0 += accS[j][0] + accS[j][1];
            rs1 += accS[j][2] + accS[j][3];
        }
        rs0 += __shfl_xor_sync(0xffffffffu, rs0, 1);
        rs0 += __shfl_xor_sync(0xffffffffu, rs0, 2);
        rs1 += __shfl_xor_sync(0xffffffffu, rs1, 1);
        rs1 += __shfl_xor_sync(0xffffffffu, rs1, 2);
        l0 = l0 * al0 + rs0;
        l1 = l1 * al1 + rs1;
        #pragma unroll
        for (int j = 0; j < 8; j++) {
            accO[j][0] *= al0; accO[j][1] *= al0;
            accO[j][2] *= al1; accO[j][3] *= al1;
        }

        #pragma unroll
        for (int c = 0; c < 4; c++) {
            uint32_t a0 = packbf(accS[2 * c][0],     accS[2 * c][1]);
            uint32_t a1 = packbf(accS[2 * c][2],     accS[2 * c][3]);
            uint32_t a2 = packbf(accS[2 * c + 1][0], accS[2 * c + 1][1]);
            uint32_t a3 = packbf(accS[2 * c + 1][2], accS[2 * c + 1][3]);
            #pragma unroll
            for (int dg = 0; dg < 4; dg++) {
                uint4 bt = ldsm4t(bV + (uint32_t)((c * 16 + ((lane >> 3) & 1) * 8 + (lane & 7)) * FST
                                                  + dg * 16 + (lane >> 4) * 8) * 2);
                mma_bf16(accO[2 * dg],     a0, a1, a2, a3, bt.x, bt.y);
                mma_bf16(accO[2 * dg + 1], a0, a1, a2, a3, bt.z, bt.w);
            }
        }
        __syncthreads();
        buf ^= 1;
    }

    float li0 = 1.f / l0, li1 = 1.f / l1;
    int r0 = lane >> 2, cbm = (lane & 3) * 2;
    int row0 = t0 + wid * 16 + r0;
    #pragma unroll
    for (int j = 0; j < 8; j++) {
        int col = head * HDIM + j * 8 + cbm;
        *(bf162*)(O + (size_t)row0 * DMODEL + col) =
            __floats2bfloat162_rn(accO[j][0] * li0, accO[j][1] * li0);
        *(bf162*)(O + (size_t)(row0 + 8) * DMODEL + col) =
            __floats2bfloat162_rn(accO[j][2] * li1, accO[j][3] * li1);
    }
}

// ---------------- misc small kernels ----------------
__global__ void zero_kernel(float* __restrict__ p, int n) {
    int i = blockIdx.x * blockDim.x + threadIdx.x;
    if (i < n) p[i] = 0.f;
}
__global__ void tgt_kernel(const bf16* __restrict__ XR, const float* __restrict__ u_emb,
                           const int* __restrict__ y, float* __restrict__ tgt) {
    int row = blockIdx.x * 4 + (threadIdx.x >> 5);
    int lane = threadIdx.x & 31;
    if (row >= TT) return;
    int t = y[row];
    const bf16* h = XR + (size_t)row * DMODEL;
    const float* u = u_emb + (size_t)t * 512;
    float s = 0.f;
    for (int i = lane * 4; i < 512; i += 128) {
        bf162 h0 = *(const bf162*)(h + i);
        bf162 h1 = *(const bf162*)(h + i + 2);
        float4 uv = *(const float4*)(u + i);
        s += __bfloat162float(h0.x) * uv.x + __bfloat162float(h0.y) * uv.y
           + __bfloat162float(h1.x) * uv.z + __bfloat162float(h1.y) * uv.w;
    }
    #pragma unroll
    for (int off = 16; off; off >>= 1) s += __shfl_xor_sync(0xffffffffu, s, off);
    if (lane == 0) tgt[row] = 30.f * tanhf(s * (1.f / 30.f));
}
__global__ void loss_kernel(const float* __restrict__ sumexp, const float* __restrict__ tgt,
                            float* __restrict__ out) {
    float s = 0.f;
    for (int i = threadIdx.x; i < TT; i += 256)
        s += logf(sumexp[i]) - tgt[i];
    float tot = block_sum_256(s);
    if (threadIdx.x == 0) out[0] = tot * (1.f / TT);
}

// ---------------- host orchestration ----------------
static inline void gemm_launch(const bf16* A, int lda, const bf16* W,
                               float* Cf, bf16* Ch, float* Csk, int ldc,
                               const float* scale, float* sumexp,
                               int M, int N, int K, int mode) {
    dim3 grid((N + 127) / 128, M / 128);
    gemm_bf16_kernel<<<grid, 256, GEMM_SMEM>>>(A, lda, W, Cf, Ch, Csk, ldc,
                                               scale, sumexp, M, N, K, mode);
}

extern "C" void kernel_launch(void* const* d_in, const int* in_sizes, int n_in,
                              void* d_out, int out_size) {
    const int*   ids     = (const int*)d_in[0];
    const int*   y       = (const int*)d_in[1];
    const float* u_emb   = (const float*)d_in[2];
    const float* b_emb   = (const float*)d_in[3];
    const float* Wq      = (const float*)d_in[4];
    const float* Wk      = (const float*)d_in[5];
    const float* Wv      = (const float*)d_in[6];
    const float* Wo      = (const float*)d_in[7];
    const float* qg      = (const float*)d_in[8];
    const float* a_scale = (const float*)d_in[9];
    const float* m_scale = (const float*)d_in[10];
    const float* rm      = (const float*)d_in[11];
    const float* Wf      = (const float*)d_in[12];
    const float* Wo2     = (const float*)d_in[13];
    const float* sw      = (const float*)d_in[14];

    cudaFuncSetAttribute(gemm_bf16_kernel, cudaFuncAttributeMaxDynamicSharedMemorySize, GEMM_SMEM);

    float *X, *X0, *QKV, *SK, *COS, *SIN, *SUM, *TGT;
    bf16 *XRh, *MHh, *ATTh, *Qh, *Kh, *Vh, *WQKVh, *WOh, *WFh, *WO2h, *UEh;
    cudaGetSymbolAddress((void**)&X,     g_X);
    cudaGetSymbolAddress((void**)&X0,    g_X0);
    cudaGetSymbolAddress((void**)&QKV,   g_QKV);
    cudaGetSymbolAddress((void**)&SK,    g_SK);
    cudaGetSymbolAddress((void**)&COS,   g_COS);
    cudaGetSymbolAddress((void**)&SIN,   g_SIN);
    cudaGetSymbolAddress((void**)&SUM,   g_SUMEXP);
    cudaGetSymbolAddress((void**)&TGT,   g_TGT);
    cudaGetSymbolAddress((void**)&XRh,   g_XRh);
    cudaGetSymbolAddress((void**)&MHh,   g_MHh);
    cudaGetSymbolAddress((void**)&ATTh,  g_ATTh);
    cudaGetSymbolAddress((void**)&Qh,    g_Qh);
    cudaGetSymbolAddress((void**)&Kh,    g_Kh);
    cudaGetSymbolAddress((void**)&Vh,    g_Vh);
    cudaGetSymbolAddress((void**)&WQKVh, g_WQKVh);
    cudaGetSymbolAddress((void**)&WOh,   g_WOh);
    cudaGetSymbolAddress((void**)&WFh,   g_WFh);
    cudaGetSymbolAddress((void**)&WO2h,  g_WO2h);
    cudaGetSymbolAddress((void**)&UEh,   g_UEh);

    // prologue (4 launches so the 6th launch overall is the first GEMM for ncu -s 5 -c 1)
    rope_table_kernel<<<(SEQ * 32 + 255) / 256, 256>>>(COS, SIN);
    {
        int tot = LNUM * QKVD * (DMODEL / 4);
        pack_qkv_kernel<<<(tot + 255) / 256, 256>>>(Wq, Wk, Wv, (bf162*)WQKVh);
        int n1 = LNUM * DMODEL * DMODEL / 4;
        int n2 = LNUM * MLPD * DMODEL / 4;
        int n4 = VSZ * 512 / 4;
        long totc = (long)n1 + n2 + n2 + n4;
        f2h_all_kernel<<<(int)((totc + 255) / 256), 256>>>(
            (const float4*)Wo,  (bf162*)WOh,  n1,
            (const float4*)Wf,  (bf162*)WFh,  n2,
            (const float4*)Wo2, (bf162*)WO2h, n2,
            (const float4*)u_emb, (bf162*)UEh, n4);
    }
    embed_kernel<<<TT, 256>>>(ids, u_emb, b_emb, X, X0);

    auto run_block = [&](int l, const float* skip, const float* swv, float* skstore) {
        mix_rmsn_kernel<<<TT, 256>>>(X, X0, XRh, rm + (size_t)l * 2 * DMODEL, skip, swv);
        gemm_launch(XRh, DMODEL, WQKVh + (size_t)l * QKVD * DMODEL, QKV, nullptr, nullptr, QKVD,
                    nullptr, nullptr, TT, QKVD, DMODEL, 0);
        qkrope_kernel<<<TT * (NH + 2 * NKV) / 8, 256>>>(QKV, Qh, Kh, Vh, COS, SIN,
                                                        qg + (size_t)l * NH);
        flash_mma_kernel<<<dim3(32, 32), 128>>>(Qh, Kh, Vh, ATTh);
        gemm_launch(ATTh, DMODEL, WOh + (size_t)l * DMODEL * DMODEL, X, nullptr, nullptr, DMODEL,
                    a_scale + (size_t)l * DMODEL, nullptr, TT, DMODEL, DMODEL, 1);
        rmsn_kernel<<<TT, 256>>>(X, XRh);
        gemm_launch(XRh, DMODEL, WFh + (size_t)l * MLPD * DMODEL, nullptr, MHh, nullptr, MLPD,
                    nullptr, nullptr, TT, MLPD, DMODEL, 2);
        gemm_launch(MHh, MLPD, WO2h + (size_t)l * DMODEL * MLPD, X, nullptr, skstore, DMODEL,
                    m_scale + (size_t)l * DMODEL, nullptr, TT, DMODEL, MLPD, 1);
    };

    // forward pass; skip stash fused into the Wo2 GEMM epilogue
    for (int i = 0; i < LNUM; i++)
        run_block(i, nullptr, nullptr, SK + (size_t)i * TT * DMODEL);
    // reverse pass with skips: h = h + sw[i]*sk[L-1-i]; block params j = L-1-i
    for (int i = 0; i < LNUM; i++) {
        int j = LNUM - 1 - i;
        run_block(j, SK + (size_t)j * TT * DMODEL, sw + (size_t)i * DMODEL, nullptr);
    }

    // final norm + loss
    rmsn_kernel<<<TT, 256>>>(X, XRh);
    zero_kernel<<<(TT + 255) / 256, 256>>>(SUM, TT);
    gemm_launch(XRh, DMODEL, UEh, nullptr, nullptr, nullptr, VSZ, nullptr, SUM, TT, VSZ, 512, 3);
    tgt_kernel<<<TT / 4, 128>>>(XRh, u_emb, y, TGT);
    loss_kernel<<<1, 256>>>(SUM, TGT, (float*)d_out);
}